// round 2
// baseline (speedup 1.0000x reference)
#include <cuda_runtime.h>
#include <math.h>

#define BATCH 4
#define SEQ   2048
#define DIM   1024
#define NH    16
#define DHEAD 64
#define HD    (NH*DHEAD)       // 1024
#define MTOT  (BATCH*SEQ)      // 8192
#define SCALE 0.125f

// Scratch (device globals: allocation-free per harness rules)
__device__ float g_q[(size_t)MTOT*HD];
__device__ float g_k[(size_t)MTOT*HD];
__device__ float g_v[(size_t)MTOT*HD];
__device__ float g_att[(size_t)MTOT*HD];

// ---------------------------------------------------------------------------
// SGEMM: C[M,N] = A[M,K] @ B[K,N], all row-major fp32.
// 128x128 tile, BK=16, 256 threads, 8x8 micro-tile.
// ---------------------------------------------------------------------------
#define BM 128
#define BN 128
#define BK 16

__global__ __launch_bounds__(256) void sgemm_kernel(
    const float* __restrict__ A, const float* __restrict__ B,
    float* __restrict__ C, int M, int N, int K)
{
    __shared__ __align__(16) float As[BK][BM + 4];
    __shared__ __align__(16) float Bs[BK][BN + 4];

    const int tid = threadIdx.x;
    const int tx  = tid & 15;
    const int ty  = tid >> 4;
    const int bm  = blockIdx.y * BM;
    const int bn  = blockIdx.x * BN;

    float acc[8][8];
#pragma unroll
    for (int i = 0; i < 8; i++)
#pragma unroll
        for (int j = 0; j < 8; j++) acc[i][j] = 0.f;

    for (int k0 = 0; k0 < K; k0 += BK) {
        // Load A tile (128x16), store transposed into As[k][m]
#pragma unroll
        for (int f = tid; f < BM * BK / 4; f += 256) {
            int row = f >> 2;            // 0..127
            int col = (f & 3) << 2;      // 0,4,8,12
            float4 t = *(const float4*)(A + (long)(bm + row) * K + k0 + col);
            As[col + 0][row] = t.x;
            As[col + 1][row] = t.y;
            As[col + 2][row] = t.z;
            As[col + 3][row] = t.w;
        }
        // Load B tile (16x128) straight
#pragma unroll
        for (int f = tid; f < BK * BN / 4; f += 256) {
            int row = f >> 5;            // 0..15
            int col = (f & 31) << 2;     // 0..124
            *(float4*)&Bs[row][col] =
                *(const float4*)(B + (long)(k0 + row) * N + bn + col);
        }
        __syncthreads();

#pragma unroll
        for (int k = 0; k < BK; k++) {
            float a[8], b[8];
            *(float4*)&a[0] = *(float4*)&As[k][ty * 8];
            *(float4*)&a[4] = *(float4*)&As[k][ty * 8 + 4];
            *(float4*)&b[0] = *(float4*)&Bs[k][tx * 8];
            *(float4*)&b[4] = *(float4*)&Bs[k][tx * 8 + 4];
#pragma unroll
            for (int i = 0; i < 8; i++)
#pragma unroll
                for (int j = 0; j < 8; j++)
                    acc[i][j] += a[i] * b[j];
        }
        __syncthreads();
    }

#pragma unroll
    for (int i = 0; i < 8; i++) {
#pragma unroll
        for (int j4 = 0; j4 < 8; j4 += 4) {
            float4 t = make_float4(acc[i][j4], acc[i][j4 + 1],
                                   acc[i][j4 + 2], acc[i][j4 + 3]);
            *(float4*)(C + (long)(bm + ty * 8 + i) * N + bn + tx * 8 + j4) = t;
        }
    }
}

// ---------------------------------------------------------------------------
// Causal flash attention, fp32. Layouts: q/k/v/o are [B, S, H, DH].
// Block: one (b,h) x 128-query tile. 256 threads: ty(16)->8 query rows each,
// tx(16)->4 key cols / 4 dh cols each. K stored dh-major (transposed) in smem
// to avoid LDS bank conflicts on the tx-indexed reads.
// ---------------------------------------------------------------------------
#define BQ  128
#define BKV 64
#define QS_S (DHEAD + 4)   // 68
#define KS_S (BKV + 4)     // 68 (transposed: rows = dh, cols = key)
#define VS_S (DHEAD + 4)
#define PS_S (BKV + 4)

#define ATTN_SMEM_FLOATS (BQ*QS_S + DHEAD*KS_S + BKV*VS_S + BQ*PS_S)

__global__ __launch_bounds__(256) void attn_kernel(
    const float* __restrict__ Q, const float* __restrict__ K,
    const float* __restrict__ V, float* __restrict__ O)
{
    extern __shared__ __align__(16) float sm[];
    float* Qs  = sm;                         // [BQ][QS_S]
    float* Kst = Qs  + BQ * QS_S;            // [DHEAD][KS_S]  (transposed)
    float* Vs  = Kst + DHEAD * KS_S;         // [BKV][VS_S]
    float* Ps  = Vs  + BKV * VS_S;           // [BQ][PS_S]

    const int tid = threadIdx.x;
    const int tx  = tid & 15;
    const int ty  = tid >> 4;
    const int bh  = blockIdx.y;
    const int b   = bh >> 4;                 // / NH
    const int h   = bh & 15;                 // % NH
    // reverse order: heavy (late) query tiles first for load balance
    const int qt  = (int)gridDim.x - 1 - (int)blockIdx.x;
    const int q0  = qt * BQ;

    // Load Q tile
    const float* qbase = Q + ((long)(b * SEQ + q0) * NH + h) * DHEAD;
#pragma unroll
    for (int f = tid; f < BQ * DHEAD / 4; f += 256) {
        int row = f >> 4;
        int col = (f & 15) << 2;
        *(float4*)&Qs[row * QS_S + col] =
            *(const float4*)(qbase + (long)row * HD + col);
    }

    float m[8], l[8], acc[8][4];
#pragma unroll
    for (int i = 0; i < 8; i++) {
        m[i] = -1e30f; l[i] = 0.f;
#pragma unroll
        for (int j = 0; j < 4; j++) acc[i][j] = 0.f;
    }

    const int kend = q0 + BQ;   // causal: keys < q0+BQ
    for (int k0 = 0; k0 < kend; k0 += BKV) {
        __syncthreads();  // protect Kst/Vs/Ps from previous iteration reads

        const float* kbase = K + ((long)(b * SEQ + k0) * NH + h) * DHEAD;
        const float* vbase = V + ((long)(b * SEQ + k0) * NH + h) * DHEAD;
#pragma unroll
        for (int f = tid; f < BKV * DHEAD / 4; f += 256) {
            int row = f >> 4;            // key index 0..63
            int col = (f & 15) << 2;     // dh 0..60
            float4 kv = *(const float4*)(kbase + (long)row * HD + col);
            Kst[(col + 0) * KS_S + row] = kv.x;
            Kst[(col + 1) * KS_S + row] = kv.y;
            Kst[(col + 2) * KS_S + row] = kv.z;
            Kst[(col + 3) * KS_S + row] = kv.w;
            *(float4*)&Vs[row * VS_S + col] =
                *(const float4*)(vbase + (long)row * HD + col);
        }
        __syncthreads();

        // S = Q @ K^T  (8 rows x 4 cols per thread)
        float s[8][4];
#pragma unroll
        for (int i = 0; i < 8; i++)
#pragma unroll
            for (int j = 0; j < 4; j++) s[i][j] = 0.f;

#pragma unroll 4
        for (int kk = 0; kk < DHEAD; kk += 4) {
            float4 qv[8], kv[4];
#pragma unroll
            for (int i = 0; i < 8; i++)
                qv[i] = *(float4*)&Qs[(ty * 8 + i) * QS_S + kk];
#pragma unroll
            for (int t = 0; t < 4; t++)
                kv[t] = *(float4*)&Kst[(kk + t) * KS_S + tx * 4];
#pragma unroll
            for (int i = 0; i < 8; i++) {
                s[i][0] += qv[i].x * kv[0].x + qv[i].y * kv[1].x
                         + qv[i].z * kv[2].x + qv[i].w * kv[3].x;
                s[i][1] += qv[i].x * kv[0].y + qv[i].y * kv[1].y
                         + qv[i].z * kv[2].y + qv[i].w * kv[3].y;
                s[i][2] += qv[i].x * kv[0].z + qv[i].y * kv[1].z
                         + qv[i].z * kv[2].z + qv[i].w * kv[3].z;
                s[i][3] += qv[i].x * kv[0].w + qv[i].y * kv[1].w
                         + qv[i].z * kv[2].w + qv[i].w * kv[3].w;
            }
        }

        // online softmax (rows owned by consecutive 16 lanes -> shfl reduce)
#pragma unroll
        for (int i = 0; i < 8; i++) {
            const int gi = q0 + ty * 8 + i;
            float mx = -1e30f;
#pragma unroll
            for (int j = 0; j < 4; j++) {
                int gj = k0 + tx * 4 + j;
                float val = s[i][j] * SCALE;
                val = (gj > gi) ? -1e30f : val;
                s[i][j] = val;
                mx = fmaxf(mx, val);
            }
#pragma unroll
            for (int d = 8; d > 0; d >>= 1)
                mx = fmaxf(mx, __shfl_xor_sync(0xffffffffu, mx, d));
            float mn = fmaxf(m[i], mx);
            float alpha = __expf(m[i] - mn);
            m[i] = mn;
            float4 p;
            p.x = __expf(s[i][0] - mn);
            p.y = __expf(s[i][1] - mn);
            p.z = __expf(s[i][2] - mn);
            p.w = __expf(s[i][3] - mn);
            float rs = p.x + p.y + p.z + p.w;
#pragma unroll
            for (int d = 8; d > 0; d >>= 1)
                rs += __shfl_xor_sync(0xffffffffu, rs, d);
            l[i] = l[i] * alpha + rs;
            acc[i][0] *= alpha; acc[i][1] *= alpha;
            acc[i][2] *= alpha; acc[i][3] *= alpha;
            *(float4*)&Ps[(ty * 8 + i) * PS_S + tx * 4] = p;
        }
        __syncthreads();

        // O += P @ V
#pragma unroll 4
        for (int kk = 0; kk < BKV; kk += 4) {
            float4 pv[8], vv[4];
#pragma unroll
            for (int i = 0; i < 8; i++)
                pv[i] = *(float4*)&Ps[(ty * 8 + i) * PS_S + kk];
#pragma unroll
            for (int t = 0; t < 4; t++)
                vv[t] = *(float4*)&Vs[(kk + t) * VS_S + tx * 4];
#pragma unroll
            for (int i = 0; i < 8; i++) {
                acc[i][0] += pv[i].x * vv[0].x + pv[i].y * vv[1].x
                           + pv[i].z * vv[2].x + pv[i].w * vv[3].x;
                acc[i][1] += pv[i].x * vv[0].y + pv[i].y * vv[1].y
                           + pv[i].z * vv[2].y + pv[i].w * vv[3].y;
                acc[i][2] += pv[i].x * vv[0].z + pv[i].y * vv[1].z
                           + pv[i].z * vv[2].z + pv[i].w * vv[3].z;
                acc[i][3] += pv[i].x * vv[0].w + pv[i].y * vv[1].w
                           + pv[i].z * vv[2].w + pv[i].w * vv[3].w;
            }
        }
    }

    // normalize + write [B,S,H,DH]
    float* obase = O + ((long)(b * SEQ + q0) * NH + h) * DHEAD;
#pragma unroll
    for (int i = 0; i < 8; i++) {
        float inv = 1.f / l[i];
        float4 t = make_float4(acc[i][0] * inv, acc[i][1] * inv,
                               acc[i][2] * inv, acc[i][3] * inv);
        *(float4*)(obase + (long)(ty * 8 + i) * HD + tx * 4) = t;
    }
}

// ---------------------------------------------------------------------------
extern "C" void kernel_launch(void* const* d_in, const int* in_sizes, int n_in,
                              void* d_out, int out_size)
{
    const float* x_q = (const float*)d_in[0];
    const float* x_k = (const float*)d_in[1];
    const float* x_v = (const float*)d_in[2];
    // d_in[3] = mask (bool) — causal, computed analytically in-kernel
    const float* Wq  = (const float*)d_in[4];
    const float* Wk  = (const float*)d_in[5];
    const float* Wv  = (const float*)d_in[6];
    const float* Wo  = (const float*)d_in[7];
    float* out = (float*)d_out;

    float *q, *k, *v, *att;
    cudaGetSymbolAddress((void**)&q,   g_q);
    cudaGetSymbolAddress((void**)&k,   g_k);
    cudaGetSymbolAddress((void**)&v,   g_v);
    cudaGetSymbolAddress((void**)&att, g_att);

    dim3 gproj(HD / BN, MTOT / BM);   // (8, 64)
    sgemm_kernel<<<gproj, 256>>>(x_q, Wq, q, MTOT, HD, DIM);
    sgemm_kernel<<<gproj, 256>>>(x_k, Wk, k, MTOT, HD, DIM);
    sgemm_kernel<<<gproj, 256>>>(x_v, Wv, v, MTOT, HD, DIM);

    size_t smem = (size_t)ATTN_SMEM_FLOATS * sizeof(float);   // 104448 B
    cudaFuncSetAttribute(attn_kernel,
                         cudaFuncAttributeMaxDynamicSharedMemorySize,
                         (int)smem);
    attn_kernel<<<dim3(SEQ / BQ, BATCH * NH), 256, smem>>>(q, k, v, att);

    dim3 gout(DIM / BN, MTOT / BM);   // (8, 64)
    sgemm_kernel<<<gout, 256>>>(att, Wo, out, MTOT, DIM, HD);
}

// round 5
// speedup vs baseline: 1.6121x; 1.6121x over previous
#include <cuda_runtime.h>
#include <cuda_bf16.h>
#include <cstdint>
#include <math.h>

#define BATCH 4
#define SEQ   2048
#define DIM   1024
#define NH    16
#define DHEAD 64
#define HD    (NH*DHEAD)       // 1024
#define MTOT  (BATCH*SEQ)      // 8192
#define SCALE 0.125f

// ---------------------------------------------------------------------------
// Device-global scratch (allocation-free per harness rules)
// ---------------------------------------------------------------------------
__device__ float g_q  [(size_t)MTOT*HD];
__device__ float g_k  [(size_t)MTOT*HD];
__device__ float g_v  [(size_t)MTOT*HD];
__device__ float g_att[(size_t)MTOT*HD];
__device__ __nv_bfloat16 g_ah[(size_t)MTOT*DIM];    // activation hi
__device__ __nv_bfloat16 g_al[(size_t)MTOT*DIM];    // activation lo
__device__ __nv_bfloat16 g_wth[4][(size_t)DIM*DIM]; // transposed weights hi [N][K]
__device__ __nv_bfloat16 g_wtl[4][(size_t)DIM*DIM]; // transposed weights lo [N][K]

// ---------------------------------------------------------------------------
// PTX helpers (baseline compute_103-safe: ldmatrix + mma.sync only)
// ---------------------------------------------------------------------------
__device__ __forceinline__ uint32_t smem_u32(const void* p) {
    uint32_t a;
    asm("{ .reg .u64 t; cvta.to.shared.u64 t, %1; cvt.u32.u64 %0, t; }"
        : "=r"(a) : "l"(p));
    return a;
}

#define LDMX4(r, addr) \
    asm volatile("ldmatrix.sync.aligned.m8n8.x4.shared.b16 {%0,%1,%2,%3}, [%4];" \
        : "=r"((r)[0]), "=r"((r)[1]), "=r"((r)[2]), "=r"((r)[3]) : "r"(addr))

#define LDMX2(r, addr) \
    asm volatile("ldmatrix.sync.aligned.m8n8.x2.shared.b16 {%0,%1}, [%2];" \
        : "=r"((r)[0]), "=r"((r)[1]) : "r"(addr))

__device__ __forceinline__ void mma16816(float* d, const uint32_t* a,
                                         const uint32_t* b) {
    asm volatile(
        "mma.sync.aligned.m16n8k16.row.col.f32.bf16.bf16.f32 "
        "{%0,%1,%2,%3}, {%4,%5,%6,%7}, {%8,%9}, {%0,%1,%2,%3};"
        : "+f"(d[0]), "+f"(d[1]), "+f"(d[2]), "+f"(d[3])
        : "r"(a[0]), "r"(a[1]), "r"(a[2]), "r"(a[3]), "r"(b[0]), "r"(b[1]));
}

// ---------------------------------------------------------------------------
// Preprocessing: fp32 -> bf16 hi/lo split (elementwise)
// ---------------------------------------------------------------------------
__global__ __launch_bounds__(256) void split_act(
    const float4* __restrict__ x, __nv_bfloat162* __restrict__ hi,
    __nv_bfloat162* __restrict__ lo, int n4)
{
    int i = blockIdx.x * blockDim.x + threadIdx.x;
    if (i >= n4) return;
    float4 v = x[i];
    __nv_bfloat16 hx = __float2bfloat16(v.x);
    __nv_bfloat16 hy = __float2bfloat16(v.y);
    __nv_bfloat16 hz = __float2bfloat16(v.z);
    __nv_bfloat16 hw = __float2bfloat16(v.w);
    hi[2*i]   = __nv_bfloat162(hx, hy);
    hi[2*i+1] = __nv_bfloat162(hz, hw);
    lo[2*i]   = __nv_bfloat162(__float2bfloat16(v.x - __bfloat162float(hx)),
                               __float2bfloat16(v.y - __bfloat162float(hy)));
    lo[2*i+1] = __nv_bfloat162(__float2bfloat16(v.z - __bfloat162float(hz)),
                               __float2bfloat16(v.w - __bfloat162float(hw)));
}

// Transpose + split weights: W[K=1024,N=1024] -> Wt_hi/lo[N][K] bf16
__global__ __launch_bounds__(256) void split_wT(
    const float* __restrict__ W, __nv_bfloat16* __restrict__ Th,
    __nv_bfloat16* __restrict__ Tl)
{
    __shared__ float t[32][33];
    int n0 = blockIdx.x * 32, k0 = blockIdx.y * 32;
    int tx = threadIdx.x, ty = threadIdx.y;   // block (32, 8)
#pragma unroll
    for (int j = 0; j < 32; j += 8)
        t[ty + j][tx] = W[(size_t)(k0 + ty + j) * DIM + n0 + tx];
    __syncthreads();
#pragma unroll
    for (int j = 0; j < 32; j += 8) {
        float v = t[tx][ty + j];
        __nv_bfloat16 h = __float2bfloat16(v);
        size_t o = (size_t)(n0 + ty + j) * DIM + k0 + tx;
        Th[o] = h;
        Tl[o] = __float2bfloat16(v - __bfloat162float(h));
    }
}

// ---------------------------------------------------------------------------
// bf16-split GEMM via mma.sync (HMMA):
//   C[M,N=1024] = (Ahi+Alo)[M,K=1024] @ (Bhi+Blo)[N,K]^T
// CTA 128x128, 8 warps (2x4), warp tile 64x32, K chunk 64, single smem
// buffer, 2 CTAs/SM for load/compute overlap. 3 passes: hh + hl + lh.
// ---------------------------------------------------------------------------
#define KC   64
#define SA   72                   // smem row stride (bf16) -> 144B, LDSM conflict-free
#define ARR  (128 * SA)           // bf16 elements per array
#define GEMM_SMEM_B (4 * ARR * 2) // 73728 B

__global__ __launch_bounds__(256, 2) void tgemm(
    const __nv_bfloat16* __restrict__ Ah, const __nv_bfloat16* __restrict__ Al,
    const __nv_bfloat16* __restrict__ Bh, const __nv_bfloat16* __restrict__ Bl,
    float* __restrict__ C)
{
    extern __shared__ __align__(16) __nv_bfloat16 sm[];
    const int tid  = threadIdx.x;
    const int lane = tid & 31;
    const int warp = tid >> 5;
    const int wm   = (warp & 1) * 64;   // warp m-offset in tile
    const int wn   = (warp >> 1) * 32;  // warp n-offset in tile
    const int bm   = blockIdx.y * 128;
    const int bn   = blockIdx.x * 128;

    const uint32_t sb = smem_u32(sm);

    float acc[4][4][4];
#pragma unroll
    for (int mt = 0; mt < 4; mt++)
#pragma unroll
        for (int nt = 0; nt < 4; nt++)
#pragma unroll
            for (int r = 0; r < 4; r++) acc[mt][nt][r] = 0.f;

    // per-thread staging indices (coalesced 16B loads)
    const int lrow = tid >> 3;        // 0..31
    const int lcol = (tid & 7) * 8;   // 0..56

    // ldmatrix lane address components
    const int a_r = wm + (lane & 15);          // A row within tile
    const int a_c = (lane >> 4) * 8;           // A col sub-offset
    const int b_r = wn + (lane & 7);           // B row (n) within tile
    const int b_c = ((lane >> 3) & 1) * 8;     // B col sub-offset

    for (int c = 0; c < DIM / KC; c++) {
        const int k0 = c * KC;
        __syncthreads();   // previous chunk's ldmatrix reads done
#pragma unroll
        for (int u = 0; u < 4; u++) {
            const int row = lrow + u * 32;
            const size_t ga = (size_t)(bm + row) * DIM + k0 + lcol;
            const size_t gb = (size_t)(bn + row) * DIM + k0 + lcol;
            const int so = row * SA + lcol;
            *(uint4*)&sm[0*ARR + so] = *(const uint4*)(Ah + ga);
            *(uint4*)&sm[1*ARR + so] = *(const uint4*)(Al + ga);
            *(uint4*)&sm[2*ARR + so] = *(const uint4*)(Bh + gb);
            *(uint4*)&sm[3*ARR + so] = *(const uint4*)(Bl + gb);
        }
        __syncthreads();

#pragma unroll
        for (int ks = 0; ks < KC / 16; ks++) {
            const int kc = ks * 16;
            uint32_t af[4][4], bh2[4][2], bl2[4][2];
#pragma unroll
            for (int mt = 0; mt < 4; mt++) {
                uint32_t ad = sb + (uint32_t)(((a_r + mt*16) * SA + kc + a_c) * 2);
                LDMX4(af[mt], ad);              // A hi
            }
#pragma unroll
            for (int nt = 0; nt < 4; nt++) {
                uint32_t bd = sb + (uint32_t)((2*ARR + (b_r + nt*8) * SA + kc + b_c) * 2);
                LDMX2(bh2[nt], bd);             // B hi
                LDMX2(bl2[nt], bd + ARR * 2);   // B lo
            }
#pragma unroll
            for (int mt = 0; mt < 4; mt++)
#pragma unroll
                for (int nt = 0; nt < 4; nt++) {
                    mma16816(acc[mt][nt], af[mt], bh2[nt]);   // hi*hi
                    mma16816(acc[mt][nt], af[mt], bl2[nt]);   // hi*lo
                }
#pragma unroll
            for (int mt = 0; mt < 4; mt++) {
                uint32_t ad = sb + (uint32_t)((ARR + (a_r + mt*16) * SA + kc + a_c) * 2);
                LDMX4(af[mt], ad);              // A lo (reuse regs)
            }
#pragma unroll
            for (int mt = 0; mt < 4; mt++)
#pragma unroll
                for (int nt = 0; nt < 4; nt++)
                    mma16816(acc[mt][nt], af[mt], bh2[nt]);   // lo*hi
        }
    }

    // epilogue: D fragment layout c0/c1 -> (gr, tg*2), c2/c3 -> (gr+8, tg*2)
    const int gr = lane >> 2, tg = lane & 3;
#pragma unroll
    for (int mt = 0; mt < 4; mt++) {
#pragma unroll
        for (int nt = 0; nt < 4; nt++) {
            float* p = C + (size_t)(bm + wm + mt*16 + gr) * DIM
                         + bn + wn + nt*8 + tg*2;
            *(float2*)p = make_float2(acc[mt][nt][0], acc[mt][nt][1]);
            *(float2*)(p + 8 * DIM) = make_float2(acc[mt][nt][2], acc[mt][nt][3]);
        }
    }
}

// ---------------------------------------------------------------------------
// Causal flash attention, fp32 (unchanged from R1/R2 passing version).
// Layout [B,S,H,DH].
// ---------------------------------------------------------------------------
#define BQ  128
#define BKV 64
#define QS_S (DHEAD + 4)
#define KS_S (BKV + 4)
#define VS_S (DHEAD + 4)
#define PS_S (BKV + 4)
#define ATTN_SMEM_FLOATS (BQ*QS_S + DHEAD*KS_S + BKV*VS_S + BQ*PS_S)

__global__ __launch_bounds__(256) void attn_kernel(
    const float* __restrict__ Q, const float* __restrict__ K,
    const float* __restrict__ V, float* __restrict__ O)
{
    extern __shared__ __align__(16) float smf[];
    float* Qs  = smf;
    float* Kst = Qs  + BQ * QS_S;
    float* Vs  = Kst + DHEAD * KS_S;
    float* Ps  = Vs  + BKV * VS_S;

    const int tid = threadIdx.x;
    const int tx  = tid & 15;
    const int ty  = tid >> 4;
    const int bh  = blockIdx.y;
    const int b   = bh >> 4;
    const int h   = bh & 15;
    const int qt  = (int)gridDim.x - 1 - (int)blockIdx.x;
    const int q0  = qt * BQ;

    const float* qbase = Q + ((size_t)(b * SEQ + q0) * NH + h) * DHEAD;
#pragma unroll
    for (int f = tid; f < BQ * DHEAD / 4; f += 256) {
        int row = f >> 4;
        int col = (f & 15) << 2;
        *(float4*)&Qs[row * QS_S + col] =
            *(const float4*)(qbase + (size_t)row * HD + col);
    }

    float m[8], l[8], acc[8][4];
#pragma unroll
    for (int i = 0; i < 8; i++) {
        m[i] = -1e30f; l[i] = 0.f;
#pragma unroll
        for (int j = 0; j < 4; j++) acc[i][j] = 0.f;
    }

    const int kend = q0 + BQ;
    for (int k0 = 0; k0 < kend; k0 += BKV) {
        __syncthreads();
        const float* kbase = K + ((size_t)(b * SEQ + k0) * NH + h) * DHEAD;
        const float* vbase = V + ((size_t)(b * SEQ + k0) * NH + h) * DHEAD;
#pragma unroll
        for (int f = tid; f < BKV * DHEAD / 4; f += 256) {
            int row = f >> 4;
            int col = (f & 15) << 2;
            float4 kv = *(const float4*)(kbase + (size_t)row * HD + col);
            Kst[(col + 0) * KS_S + row] = kv.x;
            Kst[(col + 1) * KS_S + row] = kv.y;
            Kst[(col + 2) * KS_S + row] = kv.z;
            Kst[(col + 3) * KS_S + row] = kv.w;
            *(float4*)&Vs[row * VS_S + col] =
                *(const float4*)(vbase + (size_t)row * HD + col);
        }
        __syncthreads();

        float s[8][4];
#pragma unroll
        for (int i = 0; i < 8; i++)
#pragma unroll
            for (int j = 0; j < 4; j++) s[i][j] = 0.f;

#pragma unroll 4
        for (int kk = 0; kk < DHEAD; kk += 4) {
            float4 qv[8], kv[4];
#pragma unroll
            for (int i = 0; i < 8; i++)
                qv[i] = *(float4*)&Qs[(ty * 8 + i) * QS_S + kk];
#pragma unroll
            for (int t = 0; t < 4; t++)
                kv[t] = *(float4*)&Kst[(kk + t) * KS_S + tx * 4];
#pragma unroll
            for (int i = 0; i < 8; i++) {
                s[i][0] += qv[i].x * kv[0].x + qv[i].y * kv[1].x
                         + qv[i].z * kv[2].x + qv[i].w * kv[3].x;
                s[i][1] += qv[i].x * kv[0].y + qv[i].y * kv[1].y
                         + qv[i].z * kv[2].y + qv[i].w * kv[3].y;
                s[i][2] += qv[i].x * kv[0].z + qv[i].y * kv[1].z
                         + qv[i].z * kv[2].z + qv[i].w * kv[3].z;
                s[i][3] += qv[i].x * kv[0].w + qv[i].y * kv[1].w
                         + qv[i].z * kv[2].w + qv[i].w * kv[3].w;
            }
        }

#pragma unroll
        for (int i = 0; i < 8; i++) {
            const int gi = q0 + ty * 8 + i;
            float mx = -1e30f;
#pragma unroll
            for (int j = 0; j < 4; j++) {
                int gj = k0 + tx * 4 + j;
                float val = s[i][j] * SCALE;
                val = (gj > gi) ? -1e30f : val;
                s[i][j] = val;
                mx = fmaxf(mx, val);
            }
#pragma unroll
            for (int d = 8; d > 0; d >>= 1)
                mx = fmaxf(mx, __shfl_xor_sync(0xffffffffu, mx, d));
            float mn = fmaxf(m[i], mx);
            float alpha = __expf(m[i] - mn);
            m[i] = mn;
            float4 p;
            p.x = __expf(s[i][0] - mn);
            p.y = __expf(s[i][1] - mn);
            p.z = __expf(s[i][2] - mn);
            p.w = __expf(s[i][3] - mn);
            float rs = p.x + p.y + p.z + p.w;
#pragma unroll
            for (int d = 8; d > 0; d >>= 1)
                rs += __shfl_xor_sync(0xffffffffu, rs, d);
            l[i] = l[i] * alpha + rs;
            acc[i][0] *= alpha; acc[i][1] *= alpha;
            acc[i][2] *= alpha; acc[i][3] *= alpha;
            *(float4*)&Ps[(ty * 8 + i) * PS_S + tx * 4] = p;
        }
        __syncthreads();

#pragma unroll 4
        for (int kk = 0; kk < BKV; kk += 4) {
            float4 pv[8], vv[4];
#pragma unroll
            for (int i = 0; i < 8; i++)
                pv[i] = *(float4*)&Ps[(ty * 8 + i) * PS_S + kk];
#pragma unroll
            for (int t = 0; t < 4; t++)
                vv[t] = *(float4*)&Vs[(kk + t) * VS_S + tx * 4];
#pragma unroll
            for (int i = 0; i < 8; i++) {
                acc[i][0] += pv[i].x * vv[0].x + pv[i].y * vv[1].x
                           + pv[i].z * vv[2].x + pv[i].w * vv[3].x;
                acc[i][1] += pv[i].x * vv[0].y + pv[i].y * vv[1].y
                           + pv[i].z * vv[2].y + pv[i].w * vv[3].y;
                acc[i][2] += pv[i].x * vv[0].z + pv[i].y * vv[1].z
                           + pv[i].z * vv[2].z + pv[i].w * vv[3].z;
                acc[i][3] += pv[i].x * vv[0].w + pv[i].y * vv[1].w
                           + pv[i].z * vv[2].w + pv[i].w * vv[3].w;
            }
        }
    }

    float* obase = O + ((size_t)(b * SEQ + q0) * NH + h) * DHEAD;
#pragma unroll
    for (int i = 0; i < 8; i++) {
        float inv = 1.f / l[i];
        float4 t = make_float4(acc[i][0] * inv, acc[i][1] * inv,
                               acc[i][2] * inv, acc[i][3] * inv);
        *(float4*)(obase + (size_t)(ty * 8 + i) * HD + tx * 4) = t;
    }
}

// ---------------------------------------------------------------------------
extern "C" void kernel_launch(void* const* d_in, const int* in_sizes, int n_in,
                              void* d_out, int out_size)
{
    const float* x_q = (const float*)d_in[0];
    const float* x_k = (const float*)d_in[1];
    const float* x_v = (const float*)d_in[2];
    const float* Wq  = (const float*)d_in[4];
    const float* Wk  = (const float*)d_in[5];
    const float* Wv  = (const float*)d_in[6];
    const float* Wo  = (const float*)d_in[7];
    float* out = (float*)d_out;

    float *q, *k, *v, *att;
    __nv_bfloat16 *ah, *al, *wth, *wtl;
    cudaGetSymbolAddress((void**)&q,   g_q);
    cudaGetSymbolAddress((void**)&k,   g_k);
    cudaGetSymbolAddress((void**)&v,   g_v);
    cudaGetSymbolAddress((void**)&att, g_att);
    cudaGetSymbolAddress((void**)&ah,  g_ah);
    cudaGetSymbolAddress((void**)&al,  g_al);
    cudaGetSymbolAddress((void**)&wth, g_wth);
    cudaGetSymbolAddress((void**)&wtl, g_wtl);

    cudaFuncSetAttribute(tgemm, cudaFuncAttributeMaxDynamicSharedMemorySize,
                         GEMM_SMEM_B);
    cudaFuncSetAttribute(attn_kernel,
                         cudaFuncAttributeMaxDynamicSharedMemorySize,
                         (int)(ATTN_SMEM_FLOATS * sizeof(float)));

    const int n4 = MTOT * DIM / 4;
    const dim3 wgrid(DIM / 32, DIM / 32), wblk(32, 8);
    const dim3 ggrid(DIM / 128, MTOT / 128);   // (8, 64)
    const size_t wsz = (size_t)DIM * DIM;

    // transpose + split all four weight matrices
    split_wT<<<wgrid, wblk>>>(Wq, wth + 0*wsz, wtl + 0*wsz);
    split_wT<<<wgrid, wblk>>>(Wk, wth + 1*wsz, wtl + 1*wsz);
    split_wT<<<wgrid, wblk>>>(Wv, wth + 2*wsz, wtl + 2*wsz);
    split_wT<<<wgrid, wblk>>>(Wo, wth + 3*wsz, wtl + 3*wsz);

    // projections via mma.sync bf16-split
    split_act<<<n4 / 256, 256>>>((const float4*)x_q,
        (__nv_bfloat162*)ah, (__nv_bfloat162*)al, n4);
    tgemm<<<ggrid, 256, GEMM_SMEM_B>>>(ah, al, wth + 0*wsz, wtl + 0*wsz, q);

    split_act<<<n4 / 256, 256>>>((const float4*)x_k,
        (__nv_bfloat162*)ah, (__nv_bfloat162*)al, n4);
    tgemm<<<ggrid, 256, GEMM_SMEM_B>>>(ah, al, wth + 1*wsz, wtl + 1*wsz, k);

    split_act<<<n4 / 256, 256>>>((const float4*)x_v,
        (__nv_bfloat162*)ah, (__nv_bfloat162*)al, n4);
    tgemm<<<ggrid, 256, GEMM_SMEM_B>>>(ah, al, wth + 2*wsz, wtl + 2*wsz, v);

    // attention (fp32)
    size_t asmem = (size_t)ATTN_SMEM_FLOATS * sizeof(float);
    attn_kernel<<<dim3(SEQ / BQ, BATCH * NH), 256, asmem>>>(q, k, v, att);

    // output projection
    split_act<<<n4 / 256, 256>>>((const float4*)att,
        (__nv_bfloat162*)ah, (__nv_bfloat162*)al, n4);
    tgemm<<<ggrid, 256, GEMM_SMEM_B>>>(ah, al, wth + 3*wsz, wtl + 3*wsz, out);
}

// round 7
// speedup vs baseline: 2.7451x; 1.7028x over previous
#include <cuda_runtime.h>
#include <cuda_bf16.h>
#include <cstdint>
#include <math.h>

#define BATCH 4
#define SEQ   2048
#define DIM   1024
#define NH    16
#define DHEAD 64
#define HD    (NH*DHEAD)       // 1024
#define MTOT  (BATCH*SEQ)      // 8192

// ---------------------------------------------------------------------------
// Device-global scratch (allocation-free per harness rules)
// ---------------------------------------------------------------------------
__device__ __nv_bfloat16 g_ah[(size_t)MTOT*DIM];    // activation hi (reused)
__device__ __nv_bfloat16 g_al[(size_t)MTOT*DIM];    // activation lo (reused)
__device__ __nv_bfloat16 g_qh[(size_t)MTOT*HD];
__device__ __nv_bfloat16 g_ql[(size_t)MTOT*HD];
__device__ __nv_bfloat16 g_kh[(size_t)MTOT*HD];
__device__ __nv_bfloat16 g_kl[(size_t)MTOT*HD];
__device__ __nv_bfloat16 g_vh[(size_t)MTOT*HD];
__device__ __nv_bfloat16 g_vl[(size_t)MTOT*HD];
__device__ __nv_bfloat16 g_wth[4][(size_t)DIM*DIM]; // transposed weights hi [N][K]
__device__ __nv_bfloat16 g_wtl[4][(size_t)DIM*DIM]; // transposed weights lo [N][K]

// ---------------------------------------------------------------------------
// PTX helpers (baseline compute_103-safe)
// ---------------------------------------------------------------------------
__device__ __forceinline__ uint32_t smem_u32(const void* p) {
    uint32_t a;
    asm("{ .reg .u64 t; cvta.to.shared.u64 t, %1; cvt.u32.u64 %0, t; }"
        : "=r"(a) : "l"(p));
    return a;
}

#define LDMX4(r, addr) \
    asm volatile("ldmatrix.sync.aligned.m8n8.x4.shared.b16 {%0,%1,%2,%3}, [%4];" \
        : "=r"((r)[0]), "=r"((r)[1]), "=r"((r)[2]), "=r"((r)[3]) : "r"(addr))
#define LDMX4T(r, addr) \
    asm volatile("ldmatrix.sync.aligned.m8n8.x4.trans.shared.b16 {%0,%1,%2,%3}, [%4];" \
        : "=r"((r)[0]), "=r"((r)[1]), "=r"((r)[2]), "=r"((r)[3]) : "r"(addr))
#define LDMX2(r, addr) \
    asm volatile("ldmatrix.sync.aligned.m8n8.x2.shared.b16 {%0,%1}, [%2];" \
        : "=r"((r)[0]), "=r"((r)[1]) : "r"(addr))

#define CP16(dst, src) \
    asm volatile("cp.async.cg.shared.global [%0], [%1], 16;" \
        :: "r"(dst), "l"(src))
#define CPCOMMIT() asm volatile("cp.async.commit_group;" ::: "memory")
#define CPWAIT0()  asm volatile("cp.async.wait_group 0;" ::: "memory")
#define CPWAIT1()  asm volatile("cp.async.wait_group 1;" ::: "memory")

__device__ __forceinline__ void mma16816(float* d, const uint32_t* a,
                                         uint32_t b0, uint32_t b1) {
    asm volatile(
        "mma.sync.aligned.m16n8k16.row.col.f32.bf16.bf16.f32 "
        "{%0,%1,%2,%3}, {%4,%5,%6,%7}, {%8,%9}, {%0,%1,%2,%3};"
        : "+f"(d[0]), "+f"(d[1]), "+f"(d[2]), "+f"(d[3])
        : "r"(a[0]), "r"(a[1]), "r"(a[2]), "r"(a[3]), "r"(b0), "r"(b1));
}

__device__ __forceinline__ uint32_t pack_bf16(float x, float y) {
    __nv_bfloat162 t(__float2bfloat16(x), __float2bfloat16(y));
    return *(uint32_t*)&t;
}

// ---------------------------------------------------------------------------
// fp32 -> bf16 hi/lo split (inputs only)
// ---------------------------------------------------------------------------
__global__ __launch_bounds__(256) void split_act(
    const float4* __restrict__ x, __nv_bfloat162* __restrict__ hi,
    __nv_bfloat162* __restrict__ lo, int n4)
{
    int i = blockIdx.x * blockDim.x + threadIdx.x;
    if (i >= n4) return;
    float4 v = x[i];
    __nv_bfloat16 hx = __float2bfloat16(v.x);
    __nv_bfloat16 hy = __float2bfloat16(v.y);
    __nv_bfloat16 hz = __float2bfloat16(v.z);
    __nv_bfloat16 hw = __float2bfloat16(v.w);
    hi[2*i]   = __nv_bfloat162(hx, hy);
    hi[2*i+1] = __nv_bfloat162(hz, hw);
    lo[2*i]   = __nv_bfloat162(__float2bfloat16(v.x - __bfloat162float(hx)),
                               __float2bfloat16(v.y - __bfloat162float(hy)));
    lo[2*i+1] = __nv_bfloat162(__float2bfloat16(v.z - __bfloat162float(hz)),
                               __float2bfloat16(v.w - __bfloat162float(hw)));
}

// Transpose + split weights: W[K,N] -> Wt hi/lo [N][K]
__global__ __launch_bounds__(256) void split_wT(
    const float* __restrict__ W, __nv_bfloat16* __restrict__ Th,
    __nv_bfloat16* __restrict__ Tl)
{
    __shared__ float t[32][33];
    int n0 = blockIdx.x * 32, k0 = blockIdx.y * 32;
    int tx = threadIdx.x, ty = threadIdx.y;   // block (32, 8)
#pragma unroll
    for (int j = 0; j < 32; j += 8)
        t[ty + j][tx] = W[(size_t)(k0 + ty + j) * DIM + n0 + tx];
    __syncthreads();
#pragma unroll
    for (int j = 0; j < 32; j += 8) {
        float v = t[tx][ty + j];
        __nv_bfloat16 h = __float2bfloat16(v);
        size_t o = (size_t)(n0 + ty + j) * DIM + k0 + tx;
        Th[o] = h;
        Tl[o] = __float2bfloat16(v - __bfloat162float(h));
    }
}

// ---------------------------------------------------------------------------
// bf16-split GEMM mainloop (shared by both epilogue variants)
// CTA 128x128, 8 warps (2x4), warp 64x32, K chunk 64, 2 CTAs/SM.
// ---------------------------------------------------------------------------
#define KC   64
#define SA   72
#define ARR  (128 * SA)
#define GEMM_SMEM_B (4 * ARR * 2)   // 73728 B

__device__ __forceinline__ void gemm_mainloop(
    __nv_bfloat16* sm, uint32_t sb,
    const __nv_bfloat16* __restrict__ Ah, const __nv_bfloat16* __restrict__ Al,
    const __nv_bfloat16* __restrict__ Bh, const __nv_bfloat16* __restrict__ Bl,
    int bm, int bn, float acc[4][4][4])
{
    const int tid  = threadIdx.x;
    const int lane = tid & 31;
    const int warp = tid >> 5;
    const int wm   = (warp & 1) * 64;
    const int wn   = (warp >> 1) * 32;

    const int lrow = tid >> 3;
    const int lcol = (tid & 7) * 8;
    const int a_r = wm + (lane & 15);
    const int a_c = (lane >> 4) * 8;
    const int b_r = wn + (lane & 7);
    const int b_c = ((lane >> 3) & 1) * 8;

    for (int c = 0; c < DIM / KC; c++) {
        const int k0 = c * KC;
        __syncthreads();
#pragma unroll
        for (int u = 0; u < 4; u++) {
            const int row = lrow + u * 32;
            const size_t ga = (size_t)(bm + row) * DIM + k0 + lcol;
            const size_t gb = (size_t)(bn + row) * DIM + k0 + lcol;
            const int so = row * SA + lcol;
            *(uint4*)&sm[0*ARR + so] = *(const uint4*)(Ah + ga);
            *(uint4*)&sm[1*ARR + so] = *(const uint4*)(Al + ga);
            *(uint4*)&sm[2*ARR + so] = *(const uint4*)(Bh + gb);
            *(uint4*)&sm[3*ARR + so] = *(const uint4*)(Bl + gb);
        }
        __syncthreads();

#pragma unroll
        for (int ks = 0; ks < KC / 16; ks++) {
            const int kc = ks * 16;
            uint32_t af[4][4], bh2[4][2], bl2[4][2];
#pragma unroll
            for (int mt = 0; mt < 4; mt++) {
                uint32_t ad = sb + (uint32_t)(((a_r + mt*16) * SA + kc + a_c) * 2);
                LDMX4(af[mt], ad);
            }
#pragma unroll
            for (int nt = 0; nt < 4; nt++) {
                uint32_t bd = sb + (uint32_t)((2*ARR + (b_r + nt*8) * SA + kc + b_c) * 2);
                LDMX2(bh2[nt], bd);
                LDMX2(bl2[nt], bd + ARR * 2);
            }
#pragma unroll
            for (int mt = 0; mt < 4; mt++)
#pragma unroll
                for (int nt = 0; nt < 4; nt++) {
                    mma16816(acc[mt][nt], af[mt], bh2[nt][0], bh2[nt][1]);
                    mma16816(acc[mt][nt], af[mt], bl2[nt][0], bl2[nt][1]);
                }
#pragma unroll
            for (int mt = 0; mt < 4; mt++) {
                uint32_t ad = sb + (uint32_t)((ARR + (a_r + mt*16) * SA + kc + a_c) * 2);
                LDMX4(af[mt], ad);
            }
#pragma unroll
            for (int mt = 0; mt < 4; mt++)
#pragma unroll
                for (int nt = 0; nt < 4; nt++)
                    mma16816(acc[mt][nt], af[mt], bh2[nt][0], bh2[nt][1]);
        }
    }
}

__global__ __launch_bounds__(256, 2) void tgemm_f32(
    const __nv_bfloat16* __restrict__ Ah, const __nv_bfloat16* __restrict__ Al,
    const __nv_bfloat16* __restrict__ Bh, const __nv_bfloat16* __restrict__ Bl,
    float* __restrict__ C)
{
    extern __shared__ __align__(16) __nv_bfloat16 sm[];
    const uint32_t sb = smem_u32(sm);
    const int lane = threadIdx.x & 31;
    const int warp = threadIdx.x >> 5;
    const int wm = (warp & 1) * 64, wn = (warp >> 1) * 32;
    const int bm = blockIdx.y * 128, bn = blockIdx.x * 128;

    float acc[4][4][4];
#pragma unroll
    for (int mt = 0; mt < 4; mt++)
#pragma unroll
        for (int nt = 0; nt < 4; nt++)
#pragma unroll
            for (int r = 0; r < 4; r++) acc[mt][nt][r] = 0.f;

    gemm_mainloop(sm, sb, Ah, Al, Bh, Bl, bm, bn, acc);

    const int gr = lane >> 2, tg = lane & 3;
#pragma unroll
    for (int mt = 0; mt < 4; mt++)
#pragma unroll
        for (int nt = 0; nt < 4; nt++) {
            float* p = C + (size_t)(bm + wm + mt*16 + gr) * DIM
                         + bn + wn + nt*8 + tg*2;
            *(float2*)p = make_float2(acc[mt][nt][0], acc[mt][nt][1]);
            *(float2*)(p + 8 * DIM) = make_float2(acc[mt][nt][2], acc[mt][nt][3]);
        }
}

__global__ __launch_bounds__(256, 2) void tgemm_bf16(
    const __nv_bfloat16* __restrict__ Ah, const __nv_bfloat16* __restrict__ Al,
    const __nv_bfloat16* __restrict__ Bh, const __nv_bfloat16* __restrict__ Bl,
    __nv_bfloat16* __restrict__ Oh, __nv_bfloat16* __restrict__ Ol)
{
    extern __shared__ __align__(16) __nv_bfloat16 sm[];
    const uint32_t sb = smem_u32(sm);
    const int lane = threadIdx.x & 31;
    const int warp = threadIdx.x >> 5;
    const int wm = (warp & 1) * 64, wn = (warp >> 1) * 32;
    const int bm = blockIdx.y * 128, bn = blockIdx.x * 128;

    float acc[4][4][4];
#pragma unroll
    for (int mt = 0; mt < 4; mt++)
#pragma unroll
        for (int nt = 0; nt < 4; nt++)
#pragma unroll
            for (int r = 0; r < 4; r++) acc[mt][nt][r] = 0.f;

    gemm_mainloop(sm, sb, Ah, Al, Bh, Bl, bm, bn, acc);

    const int gr = lane >> 2, tg = lane & 3;
#pragma unroll
    for (int mt = 0; mt < 4; mt++)
#pragma unroll
        for (int nt = 0; nt < 4; nt++) {
#pragma unroll
            for (int hrow = 0; hrow < 2; hrow++) {
                float f0 = acc[mt][nt][hrow*2+0], f1 = acc[mt][nt][hrow*2+1];
                __nv_bfloat16 h0 = __float2bfloat16(f0);
                __nv_bfloat16 h1 = __float2bfloat16(f1);
                size_t o = (size_t)(bm + wm + mt*16 + gr + hrow*8) * DIM
                           + bn + wn + nt*8 + tg*2;
                __nv_bfloat162 hp(h0, h1);
                __nv_bfloat162 lp(__float2bfloat16(f0 - __bfloat162float(h0)),
                                  __float2bfloat16(f1 - __bfloat162float(h1)));
                *(uint32_t*)(Oh + o) = *(uint32_t*)&hp;
                *(uint32_t*)(Ol + o) = *(uint32_t*)&lp;
            }
        }
}

// ---------------------------------------------------------------------------
// Flash attention on mma.sync, bf16 hi/lo split precision.
// Block = (b,h, 128-query tile), 8 warps x 16 q-rows. KV tiles of 64,
// cp.async double-buffered. Softmax in exp2 domain. Causal.
// Outputs bf16 hi/lo directly (input to Wo GEMM).
// ---------------------------------------------------------------------------
#define AT_SA   72
#define Q_ELEMS (128*AT_SA)         // 9216 elems per Q array
#define KV_ARR  (64*AT_SA)          // 4608
#define KV_BUF  (4*KV_ARR)          // 18432
#define KV_OFF  (2*Q_ELEMS)         // 18432
#define AT_SMEM_B ((2*Q_ELEMS + 2*KV_BUF)*2)   // 110592 B
#define F_LOG2E 0.1803368801111204f  // SCALE * log2(e)

__global__ __launch_bounds__(256, 2) void attn_mma(
    const __nv_bfloat16* __restrict__ Qh, const __nv_bfloat16* __restrict__ Ql,
    const __nv_bfloat16* __restrict__ Kh, const __nv_bfloat16* __restrict__ Kl,
    const __nv_bfloat16* __restrict__ Vh, const __nv_bfloat16* __restrict__ Vl,
    __nv_bfloat16* __restrict__ Oh, __nv_bfloat16* __restrict__ Ol)
{
    extern __shared__ __align__(16) __nv_bfloat16 sa[];
    const uint32_t sb = smem_u32(sa);
    const int tid  = threadIdx.x;
    const int lane = tid & 31;
    const int w    = tid >> 5;
    const int b    = blockIdx.y >> 4;
    const int h    = blockIdx.y & 15;
    const int qt   = (int)gridDim.x - 1 - (int)blockIdx.x;
    const int q0   = qt * 128;
    const int tid4 = lane & 3;
    const int gr   = lane >> 2;

    // ---- prologue: cp.async KV tile 0 into buf 0 ----
    {
        const size_t gb = ((size_t)(b * SEQ + 0) * NH + h) * DHEAD;
        int idx = tid;
#pragma unroll
        for (int u = 0; u < 2; u++, idx += 256) {
            int row = idx >> 3, seg = (idx & 7) * 8;
            size_t go = gb + (size_t)row * HD + seg;
            uint32_t so = sb + (uint32_t)((KV_OFF + row * AT_SA + seg) * 2);
            CP16(so + 0*KV_ARR*2, Kh + go);
            CP16(so + 1*KV_ARR*2, Kl + go);
            CP16(so + 2*KV_ARR*2, Vh + go);
            CP16(so + 3*KV_ARR*2, Vl + go);
        }
        CPCOMMIT();
    }
    // ---- load Q tile (plain) ----
    {
        const size_t gq = ((size_t)(b * SEQ + q0) * NH + h) * DHEAD;
        int idx = tid;
#pragma unroll
        for (int u = 0; u < 4; u++, idx += 256) {
            int row = idx >> 3, seg = (idx & 7) * 8;
            size_t go = gq + (size_t)row * HD + seg;
            int so = row * AT_SA + seg;
            *(uint4*)&sa[so]           = *(const uint4*)(Qh + go);
            *(uint4*)&sa[Q_ELEMS + so] = *(const uint4*)(Ql + go);
        }
    }

    float o[8][4];
#pragma unroll
    for (int nt = 0; nt < 8; nt++)
#pragma unroll
        for (int r = 0; r < 4; r++) o[nt][r] = 0.f;
    float m0 = -1e30f, m1 = -1e30f, l0 = 0.f, l1 = 0.f;

    const int gi0 = q0 + w * 16 + gr;
    const int gi1 = gi0 + 8;
    const int NT  = (q0 + 128) / 64;

    // ldmatrix address components
    const int qa_r = w * 16 + (lane & 15);
    const int qa_c = (lane >> 4) * 8;
    const int kb_r = lane & 7;
    const int kb_c = ((lane >> 3) & 1) * 8;
    const int v_r  = lane & 15;
    const int v_c8 = ((lane >> 4) & 1) * 8;

    for (int t = 0; t < NT; t++) {
        const int k0  = t * 64;
        const int buf = t & 1;
        if (t + 1 < NT) {
            const int nb = buf ^ 1;
            const size_t gb = ((size_t)(b * SEQ + (t + 1) * 64) * NH + h) * DHEAD;
            int idx = tid;
#pragma unroll
            for (int u = 0; u < 2; u++, idx += 256) {
                int row = idx >> 3, seg = (idx & 7) * 8;
                size_t go = gb + (size_t)row * HD + seg;
                uint32_t so = sb + (uint32_t)((KV_OFF + nb*KV_BUF + row*AT_SA + seg) * 2);
                CP16(so + 0*KV_ARR*2, Kh + go);
                CP16(so + 1*KV_ARR*2, Kl + go);
                CP16(so + 2*KV_ARR*2, Vh + go);
                CP16(so + 3*KV_ARR*2, Vl + go);
            }
            CPCOMMIT();
            CPWAIT1();
        } else {
            CPWAIT0();
        }
        __syncthreads();

        if (k0 <= q0 + w * 16 + 15) {   // warp has at least one live row
            const uint32_t kvb = sb + (uint32_t)((KV_OFF + buf * KV_BUF) * 2);

            // ---- S = Q K^T (3-pass split) ----
            float s[8][4];
#pragma unroll
            for (int nt = 0; nt < 8; nt++)
#pragma unroll
                for (int r = 0; r < 4; r++) s[nt][r] = 0.f;

#pragma unroll
            for (int ks = 0; ks < 4; ks++) {
                const int kc = ks * 16;
                uint32_t qh4[4], ql4[4];
                LDMX4(qh4, sb + (uint32_t)((qa_r * AT_SA + kc + qa_c) * 2));
                LDMX4(ql4, sb + (uint32_t)((Q_ELEMS + qa_r * AT_SA + kc + qa_c) * 2));
#pragma unroll
                for (int nt = 0; nt < 8; nt++) {
                    uint32_t kh2[2], kl2[2];
                    uint32_t bd = kvb + (uint32_t)(((nt*8 + kb_r) * AT_SA + kc + kb_c) * 2);
                    LDMX2(kh2, bd);
                    LDMX2(kl2, bd + KV_ARR * 2);
                    mma16816(s[nt], qh4, kh2[0], kh2[1]);
                    mma16816(s[nt], qh4, kl2[0], kl2[1]);
                    mma16816(s[nt], ql4, kh2[0], kh2[1]);
                }
            }

            // ---- scale to exp2 domain + causal mask ----
            const bool need_mask = (k0 + 63 > q0 + w * 16);
#pragma unroll
            for (int nt = 0; nt < 8; nt++) {
                const int c0 = k0 + nt * 8 + tid4 * 2;
                const int c1 = c0 + 1;
                float v0 = s[nt][0] * F_LOG2E, v1 = s[nt][1] * F_LOG2E;
                float v2 = s[nt][2] * F_LOG2E, v3 = s[nt][3] * F_LOG2E;
                if (need_mask) {
                    if (c0 > gi0) v0 = -1e30f;
                    if (c1 > gi0) v1 = -1e30f;
                    if (c0 > gi1) v2 = -1e30f;
                    if (c1 > gi1) v3 = -1e30f;
                }
                s[nt][0] = v0; s[nt][1] = v1; s[nt][2] = v2; s[nt][3] = v3;
            }

            // ---- online softmax ----
            float mx0 = -1e30f, mx1 = -1e30f;
#pragma unroll
            for (int nt = 0; nt < 8; nt++) {
                mx0 = fmaxf(mx0, fmaxf(s[nt][0], s[nt][1]));
                mx1 = fmaxf(mx1, fmaxf(s[nt][2], s[nt][3]));
            }
            mx0 = fmaxf(mx0, __shfl_xor_sync(0xffffffffu, mx0, 1));
            mx0 = fmaxf(mx0, __shfl_xor_sync(0xffffffffu, mx0, 2));
            mx1 = fmaxf(mx1, __shfl_xor_sync(0xffffffffu, mx1, 1));
            mx1 = fmaxf(mx1, __shfl_xor_sync(0xffffffffu, mx1, 2));
            const float mn0 = fmaxf(m0, mx0), mn1 = fmaxf(m1, mx1);
            const float a0 = exp2f(m0 - mn0), a1 = exp2f(m1 - mn1);
            m0 = mn0; m1 = mn1;

            float rs0 = 0.f, rs1 = 0.f;
#pragma unroll
            for (int nt = 0; nt < 8; nt++) {
                s[nt][0] = exp2f(s[nt][0] - mn0);
                s[nt][1] = exp2f(s[nt][1] - mn0);
                s[nt][2] = exp2f(s[nt][2] - mn1);
                s[nt][3] = exp2f(s[nt][3] - mn1);
                rs0 += s[nt][0] + s[nt][1];
                rs1 += s[nt][2] + s[nt][3];
            }
            rs0 += __shfl_xor_sync(0xffffffffu, rs0, 1);
            rs0 += __shfl_xor_sync(0xffffffffu, rs0, 2);
            rs1 += __shfl_xor_sync(0xffffffffu, rs1, 1);
            rs1 += __shfl_xor_sync(0xffffffffu, rs1, 2);
            l0 = l0 * a0 + rs0;
            l1 = l1 * a1 + rs1;
#pragma unroll
            for (int nt = 0; nt < 8; nt++) {
                o[nt][0] *= a0; o[nt][1] *= a0;
                o[nt][2] *= a1; o[nt][3] *= a1;
            }

            // ---- O += P V (3-pass split; P split in registers) ----
            const uint32_t vhb = kvb + 2*KV_ARR*2;
            const uint32_t vlb = kvb + 3*KV_ARR*2;
#pragma unroll
            for (int ks = 0; ks < 4; ks++) {
                uint32_t ph[4], pl[4];
#pragma unroll
                for (int half = 0; half < 2; half++) {       // nt = 2ks, 2ks+1
                    const float* sp = s[2*ks + half];
#pragma unroll
                    for (int rp = 0; rp < 2; rp++) {         // row gr, gr+8
                        float f0 = sp[rp*2+0], f1 = sp[rp*2+1];
                        __nv_bfloat16 h0 = __float2bfloat16(f0);
                        __nv_bfloat16 h1 = __float2bfloat16(f1);
                        __nv_bfloat162 hp(h0, h1);
                        __nv_bfloat162 lp(__float2bfloat16(f0 - __bfloat162float(h0)),
                                          __float2bfloat16(f1 - __bfloat162float(h1)));
                        ph[half*2 + rp] = *(uint32_t*)&hp;
                        pl[half*2 + rp] = *(uint32_t*)&lp;
                    }
                }
                // A-frag order: a0=(gr,k0-7) a1=(gr+8,k0-7) a2=(gr,k8-15) a3=(gr+8,k8-15)
                uint32_t pa[4] = { ph[0], ph[1], ph[2], ph[3] };
                uint32_t pb[4] = { pl[0], pl[1], pl[2], pl[3] };

                const int krow = ks * 16 + v_r;
#pragma unroll
                for (int db = 0; db < 4; db++) {
                    uint32_t vh4[4], vl4[4];
                    uint32_t va = (uint32_t)((krow * AT_SA + db * 16 + v_c8) * 2);
                    LDMX4T(vh4, vhb + va);
                    LDMX4T(vl4, vlb + va);
                    mma16816(o[db*2],   pa, vh4[0], vh4[1]);
                    mma16816(o[db*2],   pa, vl4[0], vl4[1]);
                    mma16816(o[db*2],   pb, vh4[0], vh4[1]);
                    mma16816(o[db*2+1], pa, vh4[2], vh4[3]);
                    mma16816(o[db*2+1], pa, vl4[2], vl4[3]);
                    mma16816(o[db*2+1], pb, vh4[2], vh4[3]);
                }
            }
        }
        __syncthreads();
    }

    // ---- epilogue: normalize, split, store bf16 hi/lo [token][HD] ----
    const float i0 = 1.f / l0, i1 = 1.f / l1;
    const size_t t0 = (size_t)(b * SEQ + gi0) * HD + h * DHEAD + tid4 * 2;
    const size_t t1 = (size_t)(b * SEQ + gi1) * HD + h * DHEAD + tid4 * 2;
#pragma unroll
    for (int nt = 0; nt < 8; nt++) {
        float f0 = o[nt][0] * i0, f1 = o[nt][1] * i0;
        float f2 = o[nt][2] * i1, f3 = o[nt][3] * i1;
        __nv_bfloat16 h0 = __float2bfloat16(f0), h1 = __float2bfloat16(f1);
        __nv_bfloat16 h2 = __float2bfloat16(f2), h3 = __float2bfloat16(f3);
        __nv_bfloat162 hp0(h0, h1), hp1(h2, h3);
        __nv_bfloat162 lp0(__float2bfloat16(f0 - __bfloat162float(h0)),
                           __float2bfloat16(f1 - __bfloat162float(h1)));
        __nv_bfloat162 lp1(__float2bfloat16(f2 - __bfloat162float(h2)),
                           __float2bfloat16(f3 - __bfloat162float(h3)));
        *(uint32_t*)(Oh + t0 + nt*8) = *(uint32_t*)&hp0;
        *(uint32_t*)(Ol + t0 + nt*8) = *(uint32_t*)&lp0;
        *(uint32_t*)(Oh + t1 + nt*8) = *(uint32_t*)&hp1;
        *(uint32_t*)(Ol + t1 + nt*8) = *(uint32_t*)&lp1;
    }
}

// ---------------------------------------------------------------------------
extern "C" void kernel_launch(void* const* d_in, const int* in_sizes, int n_in,
                              void* d_out, int out_size)
{
    const float* x_q = (const float*)d_in[0];
    const float* x_k = (const float*)d_in[1];
    const float* x_v = (const float*)d_in[2];
    const float* Wq  = (const float*)d_in[4];
    const float* Wk  = (const float*)d_in[5];
    const float* Wv  = (const float*)d_in[6];
    const float* Wo  = (const float*)d_in[7];
    float* out = (float*)d_out;

    __nv_bfloat16 *ah, *al, *qh, *ql, *kh, *kl, *vh, *vl, *wth, *wtl;
    cudaGetSymbolAddress((void**)&ah,  g_ah);
    cudaGetSymbolAddress((void**)&al,  g_al);
    cudaGetSymbolAddress((void**)&qh,  g_qh);
    cudaGetSymbolAddress((void**)&ql,  g_ql);
    cudaGetSymbolAddress((void**)&kh,  g_kh);
    cudaGetSymbolAddress((void**)&kl,  g_kl);
    cudaGetSymbolAddress((void**)&vh,  g_vh);
    cudaGetSymbolAddress((void**)&vl,  g_vl);
    cudaGetSymbolAddress((void**)&wth, g_wth);
    cudaGetSymbolAddress((void**)&wtl, g_wtl);

    cudaFuncSetAttribute(tgemm_f32, cudaFuncAttributeMaxDynamicSharedMemorySize,
                         GEMM_SMEM_B);
    cudaFuncSetAttribute(tgemm_bf16, cudaFuncAttributeMaxDynamicSharedMemorySize,
                         GEMM_SMEM_B);
    cudaFuncSetAttribute(attn_mma, cudaFuncAttributeMaxDynamicSharedMemorySize,
                         AT_SMEM_B);

    const int n4 = MTOT * DIM / 4;
    const dim3 wgrid(DIM / 32, DIM / 32), wblk(32, 8);
    const dim3 ggrid(DIM / 128, MTOT / 128);   // (8, 64)
    const size_t wsz = (size_t)DIM * DIM;

    split_wT<<<wgrid, wblk>>>(Wq, wth + 0*wsz, wtl + 0*wsz);
    split_wT<<<wgrid, wblk>>>(Wk, wth + 1*wsz, wtl + 1*wsz);
    split_wT<<<wgrid, wblk>>>(Wv, wth + 2*wsz, wtl + 2*wsz);
    split_wT<<<wgrid, wblk>>>(Wo, wth + 3*wsz, wtl + 3*wsz);

    split_act<<<n4 / 256, 256>>>((const float4*)x_q,
        (__nv_bfloat162*)ah, (__nv_bfloat162*)al, n4);
    tgemm_bf16<<<ggrid, 256, GEMM_SMEM_B>>>(ah, al, wth + 0*wsz, wtl + 0*wsz, qh, ql);

    split_act<<<n4 / 256, 256>>>((const float4*)x_k,
        (__nv_bfloat162*)ah, (__nv_bfloat162*)al, n4);
    tgemm_bf16<<<ggrid, 256, GEMM_SMEM_B>>>(ah, al, wth + 1*wsz, wtl + 1*wsz, kh, kl);

    split_act<<<n4 / 256, 256>>>((const float4*)x_v,
        (__nv_bfloat162*)ah, (__nv_bfloat162*)al, n4);
    tgemm_bf16<<<ggrid, 256, GEMM_SMEM_B>>>(ah, al, wth + 2*wsz, wtl + 2*wsz, vh, vl);

    attn_mma<<<dim3(SEQ / 128, BATCH * NH), 256, AT_SMEM_B>>>(
        qh, ql, kh, kl, vh, vl, ah, al);

    tgemm_f32<<<ggrid, 256, GEMM_SMEM_B>>>(ah, al, wth + 3*wsz, wtl + 3*wsz, out);
}

// round 8
// speedup vs baseline: 2.7858x; 1.0149x over previous
#include <cuda_runtime.h>
#include <cuda_bf16.h>
#include <cstdint>
#include <math.h>

#define BATCH 4
#define SEQ   2048
#define DIM   1024
#define NH    16
#define DHEAD 64
#define HD    (NH*DHEAD)       // 1024
#define MTOT  (BATCH*SEQ)      // 8192

// ---------------------------------------------------------------------------
// Device-global scratch (allocation-free per harness rules)
// ---------------------------------------------------------------------------
__device__ __nv_bfloat16 g_xh[3][(size_t)MTOT*DIM];  // split inputs hi (q,k,v)
__device__ __nv_bfloat16 g_xl[3][(size_t)MTOT*DIM];  // split inputs lo
__device__ __nv_bfloat16 g_oh[3][(size_t)MTOT*HD];   // projected q,k,v hi
__device__ __nv_bfloat16 g_ol[3][(size_t)MTOT*HD];   // projected q,k,v lo
__device__ __nv_bfloat16 g_ah[(size_t)MTOT*DIM];     // attention out hi
__device__ __nv_bfloat16 g_al[(size_t)MTOT*DIM];     // attention out lo
__device__ __nv_bfloat16 g_wth[4][(size_t)DIM*DIM];  // W^T hi [N][K]
__device__ __nv_bfloat16 g_wtl[4][(size_t)DIM*DIM];  // W^T lo [N][K]

// ---------------------------------------------------------------------------
// PTX helpers (baseline compute_103-safe)
// ---------------------------------------------------------------------------
__device__ __forceinline__ uint32_t smem_u32(const void* p) {
    uint32_t a;
    asm("{ .reg .u64 t; cvta.to.shared.u64 t, %1; cvt.u32.u64 %0, t; }"
        : "=r"(a) : "l"(p));
    return a;
}

#define LDMX4(r, addr) \
    asm volatile("ldmatrix.sync.aligned.m8n8.x4.shared.b16 {%0,%1,%2,%3}, [%4];" \
        : "=r"((r)[0]), "=r"((r)[1]), "=r"((r)[2]), "=r"((r)[3]) : "r"(addr))
#define LDMX4T(r, addr) \
    asm volatile("ldmatrix.sync.aligned.m8n8.x4.trans.shared.b16 {%0,%1,%2,%3}, [%4];" \
        : "=r"((r)[0]), "=r"((r)[1]), "=r"((r)[2]), "=r"((r)[3]) : "r"(addr))
#define LDMX2(r, addr) \
    asm volatile("ldmatrix.sync.aligned.m8n8.x2.shared.b16 {%0,%1}, [%2];" \
        : "=r"((r)[0]), "=r"((r)[1]) : "r"(addr))

#define CP16(dst, src) \
    asm volatile("cp.async.cg.shared.global [%0], [%1], 16;" \
        :: "r"(dst), "l"(src))
#define CPCOMMIT() asm volatile("cp.async.commit_group;" ::: "memory")
#define CPWAIT0()  asm volatile("cp.async.wait_group 0;" ::: "memory")
#define CPWAIT1()  asm volatile("cp.async.wait_group 1;" ::: "memory")

__device__ __forceinline__ void mma16816(float* d, const uint32_t* a,
                                         uint32_t b0, uint32_t b1) {
    asm volatile(
        "mma.sync.aligned.m16n8k16.row.col.f32.bf16.bf16.f32 "
        "{%0,%1,%2,%3}, {%4,%5,%6,%7}, {%8,%9}, {%0,%1,%2,%3};"
        : "+f"(d[0]), "+f"(d[1]), "+f"(d[2]), "+f"(d[3])
        : "r"(a[0]), "r"(a[1]), "r"(a[2]), "r"(a[3]), "r"(b0), "r"(b1));
}

// ---------------------------------------------------------------------------
// fp32 -> bf16 hi/lo split: fused over 3 inputs via blockIdx.y
// ---------------------------------------------------------------------------
__global__ __launch_bounds__(256) void split_act3(
    const float4* __restrict__ xq, const float4* __restrict__ xk,
    const float4* __restrict__ xv, int n4)
{
    int i = blockIdx.x * blockDim.x + threadIdx.x;
    if (i >= n4) return;
    const int z = blockIdx.y;
    const float4* x = (z == 0) ? xq : (z == 1) ? xk : xv;
    __nv_bfloat162* hi = (__nv_bfloat162*)g_xh[z];
    __nv_bfloat162* lo = (__nv_bfloat162*)g_xl[z];
    float4 v = x[i];
    __nv_bfloat16 hx = __float2bfloat16(v.x);
    __nv_bfloat16 hy = __float2bfloat16(v.y);
    __nv_bfloat16 hz = __float2bfloat16(v.z);
    __nv_bfloat16 hw = __float2bfloat16(v.w);
    hi[2*i]   = __nv_bfloat162(hx, hy);
    hi[2*i+1] = __nv_bfloat162(hz, hw);
    lo[2*i]   = __nv_bfloat162(__float2bfloat16(v.x - __bfloat162float(hx)),
                               __float2bfloat16(v.y - __bfloat162float(hy)));
    lo[2*i+1] = __nv_bfloat162(__float2bfloat16(v.z - __bfloat162float(hz)),
                               __float2bfloat16(v.w - __bfloat162float(hw)));
}

// Transpose + split 4 weights in one launch (blockIdx.z selects matrix)
__global__ __launch_bounds__(256) void split_wT4(
    const float* __restrict__ W0, const float* __restrict__ W1,
    const float* __restrict__ W2, const float* __restrict__ W3)
{
    __shared__ float t[32][33];
    const int z = blockIdx.z;
    const float* W = (z == 0) ? W0 : (z == 1) ? W1 : (z == 2) ? W2 : W3;
    __nv_bfloat16* Th = g_wth[z];
    __nv_bfloat16* Tl = g_wtl[z];
    int n0 = blockIdx.x * 32, k0 = blockIdx.y * 32;
    int tx = threadIdx.x, ty = threadIdx.y;   // block (32, 8)
#pragma unroll
    for (int j = 0; j < 32; j += 8)
        t[ty + j][tx] = W[(size_t)(k0 + ty + j) * DIM + n0 + tx];
    __syncthreads();
#pragma unroll
    for (int j = 0; j < 32; j += 8) {
        float v = t[tx][ty + j];
        __nv_bfloat16 h = __float2bfloat16(v);
        size_t o = (size_t)(n0 + ty + j) * DIM + k0 + tx;
        Th[o] = h;
        Tl[o] = __float2bfloat16(v - __bfloat162float(h));
    }
}

// ---------------------------------------------------------------------------
// bf16-split GEMM, cp.async 2-stage pipelined mainloop.
// CTA 128x128, 8 warps (2x4), warp 64x32, K chunk 32, 2 CTAs/SM.
// ---------------------------------------------------------------------------
#define KC    32
#define SA    40                  // 80B row stride: ldmatrix conflict-free
#define ARR   (128 * SA)          // 5120 elems per array
#define STAGE (4 * ARR)           // elems per stage
#define NCH   (DIM / KC)          // 32
#define GEMM_SMEM_B (2 * STAGE * 2)   // 81920 B

__device__ __forceinline__ void gemm_load_chunk(
    uint32_t sb, int st,
    const __nv_bfloat16* __restrict__ Ah, const __nv_bfloat16* __restrict__ Al,
    const __nv_bfloat16* __restrict__ Bh, const __nv_bfloat16* __restrict__ Bl,
    int bm, int bn, int k0)
{
    const int tid = threadIdx.x;
#pragma unroll
    for (int u = 0; u < 2; u++) {
        const int idx = tid + u * 256;
        const int row = idx >> 2;            // 0..127
        const int col = (idx & 3) * 8;       // 0,8,16,24
        const uint32_t so = sb + (uint32_t)((st * STAGE + row * SA + col) * 2);
        const size_t ga = (size_t)(bm + row) * DIM + k0 + col;
        const size_t gb = (size_t)(bn + row) * DIM + k0 + col;
        CP16(so + 0*ARR*2, Ah + ga);
        CP16(so + 1*ARR*2, Al + ga);
        CP16(so + 2*ARR*2, Bh + gb);
        CP16(so + 3*ARR*2, Bl + gb);
    }
}

__device__ __forceinline__ void gemm_mainloop(
    uint32_t sb,
    const __nv_bfloat16* __restrict__ Ah, const __nv_bfloat16* __restrict__ Al,
    const __nv_bfloat16* __restrict__ Bh, const __nv_bfloat16* __restrict__ Bl,
    int bm, int bn, float acc[4][4][4])
{
    const int lane = threadIdx.x & 31;
    const int warp = threadIdx.x >> 5;
    const int wm   = (warp & 1) * 64;
    const int wn   = (warp >> 1) * 32;
    const int a_r = wm + (lane & 15);
    const int a_c = (lane >> 4) * 8;
    const int b_r = wn + (lane & 7);
    const int b_c = ((lane >> 3) & 1) * 8;

    gemm_load_chunk(sb, 0, Ah, Al, Bh, Bl, bm, bn, 0);
    CPCOMMIT();

    for (int c = 0; c < NCH; c++) {
        const int st = c & 1;
        if (c + 1 < NCH) {
            gemm_load_chunk(sb, st ^ 1, Ah, Al, Bh, Bl, bm, bn, (c + 1) * KC);
            CPCOMMIT();
            CPWAIT1();
        } else {
            CPWAIT0();
        }
        __syncthreads();

        const int stOff = st * STAGE;
#pragma unroll
        for (int ks = 0; ks < KC / 16; ks++) {
            const int kc = ks * 16;
            uint32_t af[4][4], bh2[4][2], bl2[4][2];
#pragma unroll
            for (int mt = 0; mt < 4; mt++) {
                uint32_t ad = sb + (uint32_t)((stOff + (a_r + mt*16) * SA + kc + a_c) * 2);
                LDMX4(af[mt], ad);
            }
#pragma unroll
            for (int nt = 0; nt < 4; nt++) {
                uint32_t bd = sb + (uint32_t)((stOff + 2*ARR + (b_r + nt*8) * SA + kc + b_c) * 2);
                LDMX2(bh2[nt], bd);
                LDMX2(bl2[nt], bd + ARR * 2);
            }
#pragma unroll
            for (int mt = 0; mt < 4; mt++)
#pragma unroll
                for (int nt = 0; nt < 4; nt++) {
                    mma16816(acc[mt][nt], af[mt], bh2[nt][0], bh2[nt][1]);
                    mma16816(acc[mt][nt], af[mt], bl2[nt][0], bl2[nt][1]);
                }
#pragma unroll
            for (int mt = 0; mt < 4; mt++) {
                uint32_t ad = sb + (uint32_t)((stOff + ARR + (a_r + mt*16) * SA + kc + a_c) * 2);
                LDMX4(af[mt], ad);
            }
#pragma unroll
            for (int mt = 0; mt < 4; mt++)
#pragma unroll
                for (int nt = 0; nt < 4; nt++)
                    mma16816(acc[mt][nt], af[mt], bh2[nt][0], bh2[nt][1]);
        }
        __syncthreads();
    }
}

// Fused QKV projection: blockIdx.z selects input/weight/output set.
__global__ __launch_bounds__(256, 2) void tgemm_qkv()
{
    extern __shared__ __align__(16) __nv_bfloat16 sm[];
    const uint32_t sb = smem_u32(sm);
    const int z    = blockIdx.z;
    const int lane = threadIdx.x & 31;
    const int warp = threadIdx.x >> 5;
    const int wm = (warp & 1) * 64, wn = (warp >> 1) * 32;
    const int bm = blockIdx.y * 128, bn = blockIdx.x * 128;

    float acc[4][4][4];
#pragma unroll
    for (int mt = 0; mt < 4; mt++)
#pragma unroll
        for (int nt = 0; nt < 4; nt++)
#pragma unroll
            for (int r = 0; r < 4; r++) acc[mt][nt][r] = 0.f;

    gemm_mainloop(sb, g_xh[z], g_xl[z], g_wth[z], g_wtl[z], bm, bn, acc);

    __nv_bfloat16* Oh = g_oh[z];
    __nv_bfloat16* Ol = g_ol[z];
    const int gr = lane >> 2, tg = lane & 3;
#pragma unroll
    for (int mt = 0; mt < 4; mt++)
#pragma unroll
        for (int nt = 0; nt < 4; nt++)
#pragma unroll
            for (int hrow = 0; hrow < 2; hrow++) {
                float f0 = acc[mt][nt][hrow*2+0], f1 = acc[mt][nt][hrow*2+1];
                __nv_bfloat16 h0 = __float2bfloat16(f0);
                __nv_bfloat16 h1 = __float2bfloat16(f1);
                size_t o = (size_t)(bm + wm + mt*16 + gr + hrow*8) * DIM
                           + bn + wn + nt*8 + tg*2;
                __nv_bfloat162 hp(h0, h1);
                __nv_bfloat162 lp(__float2bfloat16(f0 - __bfloat162float(h0)),
                                  __float2bfloat16(f1 - __bfloat162float(h1)));
                *(uint32_t*)(Oh + o) = *(uint32_t*)&hp;
                *(uint32_t*)(Ol + o) = *(uint32_t*)&lp;
            }
}

// Output projection: A = attention out (g_ah/g_al), B = W^T[3], C fp32.
__global__ __launch_bounds__(256, 2) void tgemm_out(float* __restrict__ C)
{
    extern __shared__ __align__(16) __nv_bfloat16 sm[];
    const uint32_t sb = smem_u32(sm);
    const int lane = threadIdx.x & 31;
    const int warp = threadIdx.x >> 5;
    const int wm = (warp & 1) * 64, wn = (warp >> 1) * 32;
    const int bm = blockIdx.y * 128, bn = blockIdx.x * 128;

    float acc[4][4][4];
#pragma unroll
    for (int mt = 0; mt < 4; mt++)
#pragma unroll
        for (int nt = 0; nt < 4; nt++)
#pragma unroll
            for (int r = 0; r < 4; r++) acc[mt][nt][r] = 0.f;

    gemm_mainloop(sb, g_ah, g_al, g_wth[3], g_wtl[3], bm, bn, acc);

    const int gr = lane >> 2, tg = lane & 3;
#pragma unroll
    for (int mt = 0; mt < 4; mt++)
#pragma unroll
        for (int nt = 0; nt < 4; nt++) {
            float* p = C + (size_t)(bm + wm + mt*16 + gr) * DIM
                         + bn + wn + nt*8 + tg*2;
            *(float2*)p = make_float2(acc[mt][nt][0], acc[mt][nt][1]);
            *(float2*)(p + 8 * DIM) = make_float2(acc[mt][nt][2], acc[mt][nt][3]);
        }
}

// ---------------------------------------------------------------------------
// Flash attention on mma.sync, bf16 hi/lo split precision (as R7).
// ---------------------------------------------------------------------------
#define AT_SA   72
#define Q_ELEMS (128*AT_SA)
#define KV_ARR  (64*AT_SA)
#define KV_BUF  (4*KV_ARR)
#define KV_OFF  (2*Q_ELEMS)
#define AT_SMEM_B ((2*Q_ELEMS + 2*KV_BUF)*2)   // 110592 B
#define F_LOG2E 0.1803368801111204f            // SCALE * log2(e)

__global__ __launch_bounds__(256, 2) void attn_mma()
{
    extern __shared__ __align__(16) __nv_bfloat16 sa[];
    const __nv_bfloat16* __restrict__ Qh = g_oh[0];
    const __nv_bfloat16* __restrict__ Ql = g_ol[0];
    const __nv_bfloat16* __restrict__ Kh = g_oh[1];
    const __nv_bfloat16* __restrict__ Kl = g_ol[1];
    const __nv_bfloat16* __restrict__ Vh = g_oh[2];
    const __nv_bfloat16* __restrict__ Vl = g_ol[2];
    __nv_bfloat16* __restrict__ Oh = g_ah;
    __nv_bfloat16* __restrict__ Ol = g_al;

    const uint32_t sb = smem_u32(sa);
    const int tid  = threadIdx.x;
    const int lane = tid & 31;
    const int w    = tid >> 5;
    const int b    = blockIdx.y >> 4;
    const int h    = blockIdx.y & 15;
    const int qt   = (int)gridDim.x - 1 - (int)blockIdx.x;
    const int q0   = qt * 128;
    const int tid4 = lane & 3;
    const int gr   = lane >> 2;

    {   // prologue: KV tile 0 -> buf 0
        const size_t gb = ((size_t)(b * SEQ + 0) * NH + h) * DHEAD;
        int idx = tid;
#pragma unroll
        for (int u = 0; u < 2; u++, idx += 256) {
            int row = idx >> 3, seg = (idx & 7) * 8;
            size_t go = gb + (size_t)row * HD + seg;
            uint32_t so = sb + (uint32_t)((KV_OFF + row * AT_SA + seg) * 2);
            CP16(so + 0*KV_ARR*2, Kh + go);
            CP16(so + 1*KV_ARR*2, Kl + go);
            CP16(so + 2*KV_ARR*2, Vh + go);
            CP16(so + 3*KV_ARR*2, Vl + go);
        }
        CPCOMMIT();
    }
    {   // Q tile
        const size_t gq = ((size_t)(b * SEQ + q0) * NH + h) * DHEAD;
        int idx = tid;
#pragma unroll
        for (int u = 0; u < 4; u++, idx += 256) {
            int row = idx >> 3, seg = (idx & 7) * 8;
            size_t go = gq + (size_t)row * HD + seg;
            int so = row * AT_SA + seg;
            *(uint4*)&sa[so]           = *(const uint4*)(Qh + go);
            *(uint4*)&sa[Q_ELEMS + so] = *(const uint4*)(Ql + go);
        }
    }

    float o[8][4];
#pragma unroll
    for (int nt = 0; nt < 8; nt++)
#pragma unroll
        for (int r = 0; r < 4; r++) o[nt][r] = 0.f;
    float m0 = -1e30f, m1 = -1e30f, l0 = 0.f, l1 = 0.f;

    const int gi0 = q0 + w * 16 + gr;
    const int gi1 = gi0 + 8;
    const int NT  = (q0 + 128) / 64;

    const int qa_r = w * 16 + (lane & 15);
    const int qa_c = (lane >> 4) * 8;
    const int kb_r = lane & 7;
    const int kb_c = ((lane >> 3) & 1) * 8;
    const int v_r  = lane & 15;
    const int v_c8 = ((lane >> 4) & 1) * 8;

    for (int t = 0; t < NT; t++) {
        const int k0  = t * 64;
        const int buf = t & 1;
        if (t + 1 < NT) {
            const int nb = buf ^ 1;
            const size_t gb = ((size_t)(b * SEQ + (t + 1) * 64) * NH + h) * DHEAD;
            int idx = tid;
#pragma unroll
            for (int u = 0; u < 2; u++, idx += 256) {
                int row = idx >> 3, seg = (idx & 7) * 8;
                size_t go = gb + (size_t)row * HD + seg;
                uint32_t so = sb + (uint32_t)((KV_OFF + nb*KV_BUF + row*AT_SA + seg) * 2);
                CP16(so + 0*KV_ARR*2, Kh + go);
                CP16(so + 1*KV_ARR*2, Kl + go);
                CP16(so + 2*KV_ARR*2, Vh + go);
                CP16(so + 3*KV_ARR*2, Vl + go);
            }
            CPCOMMIT();
            CPWAIT1();
        } else {
            CPWAIT0();
        }
        __syncthreads();

        if (k0 <= q0 + w * 16 + 15) {
            const uint32_t kvb = sb + (uint32_t)((KV_OFF + buf * KV_BUF) * 2);

            float s[8][4];
#pragma unroll
            for (int nt = 0; nt < 8; nt++)
#pragma unroll
                for (int r = 0; r < 4; r++) s[nt][r] = 0.f;

#pragma unroll
            for (int ks = 0; ks < 4; ks++) {
                const int kc = ks * 16;
                uint32_t qh4[4], ql4[4];
                LDMX4(qh4, sb + (uint32_t)((qa_r * AT_SA + kc + qa_c) * 2));
                LDMX4(ql4, sb + (uint32_t)((Q_ELEMS + qa_r * AT_SA + kc + qa_c) * 2));
#pragma unroll
                for (int nt = 0; nt < 8; nt++) {
                    uint32_t kh2[2], kl2[2];
                    uint32_t bd = kvb + (uint32_t)(((nt*8 + kb_r) * AT_SA + kc + kb_c) * 2);
                    LDMX2(kh2, bd);
                    LDMX2(kl2, bd + KV_ARR * 2);
                    mma16816(s[nt], qh4, kh2[0], kh2[1]);
                    mma16816(s[nt], qh4, kl2[0], kl2[1]);
                    mma16816(s[nt], ql4, kh2[0], kh2[1]);
                }
            }

            const bool need_mask = (k0 + 63 > q0 + w * 16);
#pragma unroll
            for (int nt = 0; nt < 8; nt++) {
                const int c0 = k0 + nt * 8 + tid4 * 2;
                const int c1 = c0 + 1;
                float v0 = s[nt][0] * F_LOG2E, v1 = s[nt][1] * F_LOG2E;
                float v2 = s[nt][2] * F_LOG2E, v3 = s[nt][3] * F_LOG2E;
                if (need_mask) {
                    if (c0 > gi0) v0 = -1e30f;
                    if (c1 > gi0) v1 = -1e30f;
                    if (c0 > gi1) v2 = -1e30f;
                    if (c1 > gi1) v3 = -1e30f;
                }
                s[nt][0] = v0; s[nt][1] = v1; s[nt][2] = v2; s[nt][3] = v3;
            }

            float mx0 = -1e30f, mx1 = -1e30f;
#pragma unroll
            for (int nt = 0; nt < 8; nt++) {
                mx0 = fmaxf(mx0, fmaxf(s[nt][0], s[nt][1]));
                mx1 = fmaxf(mx1, fmaxf(s[nt][2], s[nt][3]));
            }
            mx0 = fmaxf(mx0, __shfl_xor_sync(0xffffffffu, mx0, 1));
            mx0 = fmaxf(mx0, __shfl_xor_sync(0xffffffffu, mx0, 2));
            mx1 = fmaxf(mx1, __shfl_xor_sync(0xffffffffu, mx1, 1));
            mx1 = fmaxf(mx1, __shfl_xor_sync(0xffffffffu, mx1, 2));
            const float mn0 = fmaxf(m0, mx0), mn1 = fmaxf(m1, mx1);
            const float a0 = exp2f(m0 - mn0), a1 = exp2f(m1 - mn1);
            m0 = mn0; m1 = mn1;

            float rs0 = 0.f, rs1 = 0.f;
#pragma unroll
            for (int nt = 0; nt < 8; nt++) {
                s[nt][0] = exp2f(s[nt][0] - mn0);
                s[nt][1] = exp2f(s[nt][1] - mn0);
                s[nt][2] = exp2f(s[nt][2] - mn1);
                s[nt][3] = exp2f(s[nt][3] - mn1);
                rs0 += s[nt][0] + s[nt][1];
                rs1 += s[nt][2] + s[nt][3];
            }
            rs0 += __shfl_xor_sync(0xffffffffu, rs0, 1);
            rs0 += __shfl_xor_sync(0xffffffffu, rs0, 2);
            rs1 += __shfl_xor_sync(0xffffffffu, rs1, 1);
            rs1 += __shfl_xor_sync(0xffffffffu, rs1, 2);
            l0 = l0 * a0 + rs0;
            l1 = l1 * a1 + rs1;
#pragma unroll
            for (int nt = 0; nt < 8; nt++) {
                o[nt][0] *= a0; o[nt][1] *= a0;
                o[nt][2] *= a1; o[nt][3] *= a1;
            }

            const uint32_t vhb = kvb + 2*KV_ARR*2;
            const uint32_t vlb = kvb + 3*KV_ARR*2;
#pragma unroll
            for (int ks = 0; ks < 4; ks++) {
                uint32_t pa[4], pb[4];
#pragma unroll
                for (int half = 0; half < 2; half++) {
                    const float* sp = s[2*ks + half];
#pragma unroll
                    for (int rp = 0; rp < 2; rp++) {
                        float f0 = sp[rp*2+0], f1 = sp[rp*2+1];
                        __nv_bfloat16 h0 = __float2bfloat16(f0);
                        __nv_bfloat16 h1 = __float2bfloat16(f1);
                        __nv_bfloat162 hp(h0, h1);
                        __nv_bfloat162 lp(__float2bfloat16(f0 - __bfloat162float(h0)),
                                          __float2bfloat16(f1 - __bfloat162float(h1)));
                        pa[half*2 + rp] = *(uint32_t*)&hp;
                        pb[half*2 + rp] = *(uint32_t*)&lp;
                    }
                }
                const int krow = ks * 16 + v_r;
#pragma unroll
                for (int db = 0; db < 4; db++) {
                    uint32_t vh4[4], vl4[4];
                    uint32_t va = (uint32_t)((krow * AT_SA + db * 16 + v_c8) * 2);
                    LDMX4T(vh4, vhb + va);
                    LDMX4T(vl4, vlb + va);
                    mma16816(o[db*2],   pa, vh4[0], vh4[1]);
                    mma16816(o[db*2],   pa, vl4[0], vl4[1]);
                    mma16816(o[db*2],   pb, vh4[0], vh4[1]);
                    mma16816(o[db*2+1], pa, vh4[2], vh4[3]);
                    mma16816(o[db*2+1], pa, vl4[2], vl4[3]);
                    mma16816(o[db*2+1], pb, vh4[2], vh4[3]);
                }
            }
        }
        __syncthreads();
    }

    const float i0 = 1.f / l0, i1 = 1.f / l1;
    const size_t t0 = (size_t)(b * SEQ + gi0) * HD + h * DHEAD + tid4 * 2;
    const size_t t1 = (size_t)(b * SEQ + gi1) * HD + h * DHEAD + tid4 * 2;
#pragma unroll
    for (int nt = 0; nt < 8; nt++) {
        float f0 = o[nt][0] * i0, f1 = o[nt][1] * i0;
        float f2 = o[nt][2] * i1, f3 = o[nt][3] * i1;
        __nv_bfloat16 h0 = __float2bfloat16(f0), h1 = __float2bfloat16(f1);
        __nv_bfloat16 h2 = __float2bfloat16(f2), h3 = __float2bfloat16(f3);
        __nv_bfloat162 hp0(h0, h1), hp1(h2, h3);
        __nv_bfloat162 lp0(__float2bfloat16(f0 - __bfloat162float(h0)),
                           __float2bfloat16(f1 - __bfloat162float(h1)));
        __nv_bfloat162 lp1(__float2bfloat16(f2 - __bfloat162float(h2)),
                           __float2bfloat16(f3 - __bfloat162float(h3)));
        *(uint32_t*)(Oh + t0 + nt*8) = *(uint32_t*)&hp0;
        *(uint32_t*)(Ol + t0 + nt*8) = *(uint32_t*)&lp0;
        *(uint32_t*)(Oh + t1 + nt*8) = *(uint32_t*)&hp1;
        *(uint32_t*)(Ol + t1 + nt*8) = *(uint32_t*)&lp1;
    }
}

// ---------------------------------------------------------------------------
extern "C" void kernel_launch(void* const* d_in, const int* in_sizes, int n_in,
                              void* d_out, int out_size)
{
    const float* x_q = (const float*)d_in[0];
    const float* x_k = (const float*)d_in[1];
    const float* x_v = (const float*)d_in[2];
    const float* Wq  = (const float*)d_in[4];
    const float* Wk  = (const float*)d_in[5];
    const float* Wv  = (const float*)d_in[6];
    const float* Wo  = (const float*)d_in[7];
    float* out = (float*)d_out;

    cudaFuncSetAttribute(tgemm_qkv, cudaFuncAttributeMaxDynamicSharedMemorySize,
                         GEMM_SMEM_B);
    cudaFuncSetAttribute(tgemm_out, cudaFuncAttributeMaxDynamicSharedMemorySize,
                         GEMM_SMEM_B);
    cudaFuncSetAttribute(attn_mma, cudaFuncAttributeMaxDynamicSharedMemorySize,
                         AT_SMEM_B);

    const int n4 = MTOT * DIM / 4;

    // weight transpose+split (all four) and input splits (all three)
    split_wT4<<<dim3(DIM / 32, DIM / 32, 4), dim3(32, 8)>>>(Wq, Wk, Wv, Wo);
    split_act3<<<dim3(n4 / 256, 3), 256>>>(
        (const float4*)x_q, (const float4*)x_k, (const float4*)x_v, n4);

    // fused QKV projections (grid.z = 3)
    tgemm_qkv<<<dim3(DIM / 128, MTOT / 128, 3), 256, GEMM_SMEM_B>>>();

    // attention
    attn_mma<<<dim3(SEQ / 128, BATCH * NH), 256, AT_SMEM_B>>>();

    // output projection
    tgemm_out<<<dim3(DIM / 128, MTOT / 128), 256, GEMM_SMEM_B>>>(out);
}

// round 10
// speedup vs baseline: 2.7898x; 1.0014x over previous
#include <cuda_runtime.h>
#include <cuda_bf16.h>
#include <cstdint>
#include <math.h>

#define BATCH 4
#define SEQ   2048
#define DIM   1024
#define NH    16
#define DHEAD 64
#define HD    (NH*DHEAD)       // 1024
#define MTOT  (BATCH*SEQ)      // 8192

// ---------------------------------------------------------------------------
// Device-global scratch (allocation-free per harness rules)
// ---------------------------------------------------------------------------
__device__ __nv_bfloat16 g_xh[3][(size_t)MTOT*DIM];  // split inputs hi (q,k,v)
__device__ __nv_bfloat16 g_xl[3][(size_t)MTOT*DIM];  // split inputs lo
__device__ __nv_bfloat16 g_oh[3][(size_t)MTOT*HD];   // projected q,k,v hi
__device__ __nv_bfloat16 g_ol[3][(size_t)MTOT*HD];   // projected q,k,v lo
__device__ __nv_bfloat16 g_ah[(size_t)MTOT*DIM];     // attention out hi
__device__ __nv_bfloat16 g_al[(size_t)MTOT*DIM];     // attention out lo
__device__ __nv_bfloat16 g_wth[4][(size_t)DIM*DIM];  // W^T hi [N][K]
__device__ __nv_bfloat16 g_wtl[4][(size_t)DIM*DIM];  // W^T lo [N][K]

// ---------------------------------------------------------------------------
// PTX helpers (baseline compute_103-safe)
// ---------------------------------------------------------------------------
__device__ __forceinline__ uint32_t smem_u32(const void* p) {
    uint32_t a;
    asm("{ .reg .u64 t; cvta.to.shared.u64 t, %1; cvt.u32.u64 %0, t; }"
        : "=r"(a) : "l"(p));
    return a;
}

#define LDMX4(r, addr) \
    asm volatile("ldmatrix.sync.aligned.m8n8.x4.shared.b16 {%0,%1,%2,%3}, [%4];" \
        : "=r"((r)[0]), "=r"((r)[1]), "=r"((r)[2]), "=r"((r)[3]) : "r"(addr))
#define LDMX4T(r, addr) \
    asm volatile("ldmatrix.sync.aligned.m8n8.x4.trans.shared.b16 {%0,%1,%2,%3}, [%4];" \
        : "=r"((r)[0]), "=r"((r)[1]), "=r"((r)[2]), "=r"((r)[3]) : "r"(addr))
#define LDMX2(r, addr) \
    asm volatile("ldmatrix.sync.aligned.m8n8.x2.shared.b16 {%0,%1}, [%2];" \
        : "=r"((r)[0]), "=r"((r)[1]) : "r"(addr))

#define CP16(dst, src) \
    asm volatile("cp.async.cg.shared.global [%0], [%1], 16;" \
        :: "r"(dst), "l"(src))
#define CPCOMMIT() asm volatile("cp.async.commit_group;" ::: "memory")
#define CPWAIT0()  asm volatile("cp.async.wait_group 0;" ::: "memory")
#define CPWAIT1()  asm volatile("cp.async.wait_group 1;" ::: "memory")

__device__ __forceinline__ void mma16816(float* d, const uint32_t* a,
                                         uint32_t b0, uint32_t b1) {
    asm volatile(
        "mma.sync.aligned.m16n8k16.row.col.f32.bf16.bf16.f32 "
        "{%0,%1,%2,%3}, {%4,%5,%6,%7}, {%8,%9}, {%0,%1,%2,%3};"
        : "+f"(d[0]), "+f"(d[1]), "+f"(d[2]), "+f"(d[3])
        : "r"(a[0]), "r"(a[1]), "r"(a[2]), "r"(a[3]), "r"(b0), "r"(b1));
}

// ---------------------------------------------------------------------------
// fp32 -> bf16 hi/lo split: fused over 3 inputs via blockIdx.y
// ---------------------------------------------------------------------------
__global__ __launch_bounds__(256) void split_act3(
    const float4* __restrict__ xq, const float4* __restrict__ xk,
    const float4* __restrict__ xv, int n4)
{
    int i = blockIdx.x * blockDim.x + threadIdx.x;
    if (i >= n4) return;
    const int z = blockIdx.y;
    const float4* x = (z == 0) ? xq : (z == 1) ? xk : xv;
    __nv_bfloat162* hi = (__nv_bfloat162*)g_xh[z];
    __nv_bfloat162* lo = (__nv_bfloat162*)g_xl[z];
    float4 v = x[i];
    __nv_bfloat16 hx = __float2bfloat16(v.x);
    __nv_bfloat16 hy = __float2bfloat16(v.y);
    __nv_bfloat16 hz = __float2bfloat16(v.z);
    __nv_bfloat16 hw = __float2bfloat16(v.w);
    hi[2*i]   = __nv_bfloat162(hx, hy);
    hi[2*i+1] = __nv_bfloat162(hz, hw);
    lo[2*i]   = __nv_bfloat162(__float2bfloat16(v.x - __bfloat162float(hx)),
                               __float2bfloat16(v.y - __bfloat162float(hy)));
    lo[2*i+1] = __nv_bfloat162(__float2bfloat16(v.z - __bfloat162float(hz)),
                               __float2bfloat16(v.w - __bfloat162float(hw)));
}

// Transpose + split 4 weights in one launch (blockIdx.z selects matrix)
__global__ __launch_bounds__(256) void split_wT4(
    const float* __restrict__ W0, const float* __restrict__ W1,
    const float* __restrict__ W2, const float* __restrict__ W3)
{
    __shared__ float t[32][33];
    const int z = blockIdx.z;
    const float* W = (z == 0) ? W0 : (z == 1) ? W1 : (z == 2) ? W2 : W3;
    __nv_bfloat16* Th = g_wth[z];
    __nv_bfloat16* Tl = g_wtl[z];
    int n0 = blockIdx.x * 32, k0 = blockIdx.y * 32;
    int tx = threadIdx.x, ty = threadIdx.y;   // block (32, 8)
#pragma unroll
    for (int j = 0; j < 32; j += 8)
        t[ty + j][tx] = W[(size_t)(k0 + ty + j) * DIM + n0 + tx];
    __syncthreads();
#pragma unroll
    for (int j = 0; j < 32; j += 8) {
        float v = t[tx][ty + j];
        __nv_bfloat16 h = __float2bfloat16(v);
        size_t o = (size_t)(n0 + ty + j) * DIM + k0 + tx;
        Th[o] = h;
        Tl[o] = __float2bfloat16(v - __bfloat162float(h));
    }
}

// ---------------------------------------------------------------------------
// bf16-split GEMM, cp.async 2-stage pipelined mainloop.
// CTA 128x128, 8 warps (2x4), warp 64x32, K chunk 32, 2 CTAs/SM.
// ---------------------------------------------------------------------------
#define KC    32
#define SA    40                  // 80B row stride: ldmatrix conflict-free
#define ARR   (128 * SA)          // 5120 elems per array
#define STAGE (4 * ARR)           // elems per stage
#define NCH   (DIM / KC)          // 32
#define GEMM_SMEM_B (2 * STAGE * 2)   // 81920 B

__device__ __forceinline__ void gemm_load_chunk(
    uint32_t sb, int st,
    const __nv_bfloat16* __restrict__ Ah, const __nv_bfloat16* __restrict__ Al,
    const __nv_bfloat16* __restrict__ Bh, const __nv_bfloat16* __restrict__ Bl,
    int bm, int bn, int k0)
{
    const int tid = threadIdx.x;
#pragma unroll
    for (int u = 0; u < 2; u++) {
        const int idx = tid + u * 256;
        const int row = idx >> 2;            // 0..127
        const int col = (idx & 3) * 8;       // 0,8,16,24
        const uint32_t so = sb + (uint32_t)((st * STAGE + row * SA + col) * 2);
        const size_t ga = (size_t)(bm + row) * DIM + k0 + col;
        const size_t gb = (size_t)(bn + row) * DIM + k0 + col;
        CP16(so + 0*ARR*2, Ah + ga);
        CP16(so + 1*ARR*2, Al + ga);
        CP16(so + 2*ARR*2, Bh + gb);
        CP16(so + 3*ARR*2, Bl + gb);
    }
}

__device__ __forceinline__ void gemm_mainloop(
    uint32_t sb,
    const __nv_bfloat16* __restrict__ Ah, const __nv_bfloat16* __restrict__ Al,
    const __nv_bfloat16* __restrict__ Bh, const __nv_bfloat16* __restrict__ Bl,
    int bm, int bn, float acc[4][4][4])
{
    const int lane = threadIdx.x & 31;
    const int warp = threadIdx.x >> 5;
    const int wm   = (warp & 1) * 64;
    const int wn   = (warp >> 1) * 32;
    const int a_r = wm + (lane & 15);
    const int a_c = (lane >> 4) * 8;
    const int b_r = wn + (lane & 7);
    const int b_c = ((lane >> 3) & 1) * 8;

    gemm_load_chunk(sb, 0, Ah, Al, Bh, Bl, bm, bn, 0);
    CPCOMMIT();

    for (int c = 0; c < NCH; c++) {
        const int st = c & 1;
        if (c + 1 < NCH) {
            gemm_load_chunk(sb, st ^ 1, Ah, Al, Bh, Bl, bm, bn, (c + 1) * KC);
            CPCOMMIT();
            CPWAIT1();
        } else {
            CPWAIT0();
        }
        __syncthreads();

        const int stOff = st * STAGE;
#pragma unroll
        for (int ks = 0; ks < KC / 16; ks++) {
            const int kc = ks * 16;
            uint32_t af[4][4], bh2[4][2], bl2[4][2];
#pragma unroll
            for (int mt = 0; mt < 4; mt++) {
                uint32_t ad = sb + (uint32_t)((stOff + (a_r + mt*16) * SA + kc + a_c) * 2);
                LDMX4(af[mt], ad);
            }
#pragma unroll
            for (int nt = 0; nt < 4; nt++) {
                uint32_t bd = sb + (uint32_t)((stOff + 2*ARR + (b_r + nt*8) * SA + kc + b_c) * 2);
                LDMX2(bh2[nt], bd);
                LDMX2(bl2[nt], bd + ARR * 2);
            }
#pragma unroll
            for (int mt = 0; mt < 4; mt++)
#pragma unroll
                for (int nt = 0; nt < 4; nt++) {
                    mma16816(acc[mt][nt], af[mt], bh2[nt][0], bh2[nt][1]);
                    mma16816(acc[mt][nt], af[mt], bl2[nt][0], bl2[nt][1]);
                }
#pragma unroll
            for (int mt = 0; mt < 4; mt++) {
                uint32_t ad = sb + (uint32_t)((stOff + ARR + (a_r + mt*16) * SA + kc + a_c) * 2);
                LDMX4(af[mt], ad);
            }
#pragma unroll
            for (int mt = 0; mt < 4; mt++)
#pragma unroll
                for (int nt = 0; nt < 4; nt++)
                    mma16816(acc[mt][nt], af[mt], bh2[nt][0], bh2[nt][1]);
        }
        __syncthreads();
    }
}

// Fused QKV projection: blockIdx.z selects input/weight/output set.
__global__ __launch_bounds__(256, 2) void tgemm_qkv()
{
    extern __shared__ __align__(16) __nv_bfloat16 sm[];
    const uint32_t sb = smem_u32(sm);
    const int z    = blockIdx.z;
    const int lane = threadIdx.x & 31;
    const int warp = threadIdx.x >> 5;
    const int wm = (warp & 1) * 64, wn = (warp >> 1) * 32;
    const int bm = blockIdx.y * 128, bn = blockIdx.x * 128;

    float acc[4][4][4];
#pragma unroll
    for (int mt = 0; mt < 4; mt++)
#pragma unroll
        for (int nt = 0; nt < 4; nt++)
#pragma unroll
            for (int r = 0; r < 4; r++) acc[mt][nt][r] = 0.f;

    gemm_mainloop(sb, g_xh[z], g_xl[z], g_wth[z], g_wtl[z], bm, bn, acc);

    __nv_bfloat16* Oh = g_oh[z];
    __nv_bfloat16* Ol = g_ol[z];
    const int gr = lane >> 2, tg = lane & 3;
#pragma unroll
    for (int mt = 0; mt < 4; mt++)
#pragma unroll
        for (int nt = 0; nt < 4; nt++)
#pragma unroll
            for (int hrow = 0; hrow < 2; hrow++) {
                float f0 = acc[mt][nt][hrow*2+0], f1 = acc[mt][nt][hrow*2+1];
                __nv_bfloat16 h0 = __float2bfloat16(f0);
                __nv_bfloat16 h1 = __float2bfloat16(f1);
                size_t o = (size_t)(bm + wm + mt*16 + gr + hrow*8) * DIM
                           + bn + wn + nt*8 + tg*2;
                __nv_bfloat162 hp(h0, h1);
                __nv_bfloat162 lp(__float2bfloat16(f0 - __bfloat162float(h0)),
                                  __float2bfloat16(f1 - __bfloat162float(h1)));
                *(uint32_t*)(Oh + o) = *(uint32_t*)&hp;
                *(uint32_t*)(Ol + o) = *(uint32_t*)&lp;
            }
}

// Output projection: A = attention out (g_ah/g_al), B = W^T[3], C fp32.
__global__ __launch_bounds__(256, 2) void tgemm_out(float* __restrict__ C)
{
    extern __shared__ __align__(16) __nv_bfloat16 sm[];
    const uint32_t sb = smem_u32(sm);
    const int lane = threadIdx.x & 31;
    const int warp = threadIdx.x >> 5;
    const int wm = (warp & 1) * 64, wn = (warp >> 1) * 32;
    const int bm = blockIdx.y * 128, bn = blockIdx.x * 128;

    float acc[4][4][4];
#pragma unroll
    for (int mt = 0; mt < 4; mt++)
#pragma unroll
        for (int nt = 0; nt < 4; nt++)
#pragma unroll
            for (int r = 0; r < 4; r++) acc[mt][nt][r] = 0.f;

    gemm_mainloop(sb, g_ah, g_al, g_wth[3], g_wtl[3], bm, bn, acc);

    const int gr = lane >> 2, tg = lane & 3;
#pragma unroll
    for (int mt = 0; mt < 4; mt++)
#pragma unroll
        for (int nt = 0; nt < 4; nt++) {
            float* p = C + (size_t)(bm + wm + mt*16 + gr) * DIM
                         + bn + wn + nt*8 + tg*2;
            *(float2*)p = make_float2(acc[mt][nt][0], acc[mt][nt][1]);
            *(float2*)(p + 8 * DIM) = make_float2(acc[mt][nt][2], acc[mt][nt][3]);
        }
}

// ---------------------------------------------------------------------------
// Flash attention on mma.sync, bf16 hi/lo split precision (as R7).
// ---------------------------------------------------------------------------
#define AT_SA   72
#define Q_ELEMS (128*AT_SA)
#define KV_ARR  (64*AT_SA)
#define KV_BUF  (4*KV_ARR)
#define KV_OFF  (2*Q_ELEMS)
#define AT_SMEM_B ((2*Q_ELEMS + 2*KV_BUF)*2)   // 110592 B
#define F_LOG2E 0.1803368801111204f            // SCALE * log2(e)

__global__ __launch_bounds__(256, 2) void attn_mma()
{
    extern __shared__ __align__(16) __nv_bfloat16 sa[];
    const __nv_bfloat16* __restrict__ Qh = g_oh[0];
    const __nv_bfloat16* __restrict__ Ql = g_ol[0];
    const __nv_bfloat16* __restrict__ Kh = g_oh[1];
    const __nv_bfloat16* __restrict__ Kl = g_ol[1];
    const __nv_bfloat16* __restrict__ Vh = g_oh[2];
    const __nv_bfloat16* __restrict__ Vl = g_ol[2];
    __nv_bfloat16* __restrict__ Oh = g_ah;
    __nv_bfloat16* __restrict__ Ol = g_al;

    const uint32_t sb = smem_u32(sa);
    const int tid  = threadIdx.x;
    const int lane = tid & 31;
    const int w    = tid >> 5;
    const int b    = blockIdx.y >> 4;
    const int h    = blockIdx.y & 15;
    const int qt   = (int)gridDim.x - 1 - (int)blockIdx.x;
    const int q0   = qt * 128;
    const int tid4 = lane & 3;
    const int gr   = lane >> 2;

    {   // prologue: KV tile 0 -> buf 0
        const size_t gb = ((size_t)(b * SEQ + 0) * NH + h) * DHEAD;
        int idx = tid;
#pragma unroll
        for (int u = 0; u < 2; u++, idx += 256) {
            int row = idx >> 3, seg = (idx & 7) * 8;
            size_t go = gb + (size_t)row * HD + seg;
            uint32_t so = sb + (uint32_t)((KV_OFF + row * AT_SA + seg) * 2);
            CP16(so + 0*KV_ARR*2, Kh + go);
            CP16(so + 1*KV_ARR*2, Kl + go);
            CP16(so + 2*KV_ARR*2, Vh + go);
            CP16(so + 3*KV_ARR*2, Vl + go);
        }
        CPCOMMIT();
    }
    {   // Q tile
        const size_t gq = ((size_t)(b * SEQ + q0) * NH + h) * DHEAD;
        int idx = tid;
#pragma unroll
        for (int u = 0; u < 4; u++, idx += 256) {
            int row = idx >> 3, seg = (idx & 7) * 8;
            size_t go = gq + (size_t)row * HD + seg;
            int so = row * AT_SA + seg;
            *(uint4*)&sa[so]           = *(const uint4*)(Qh + go);
            *(uint4*)&sa[Q_ELEMS + so] = *(const uint4*)(Ql + go);
        }
    }

    float o[8][4];
#pragma unroll
    for (int nt = 0; nt < 8; nt++)
#pragma unroll
        for (int r = 0; r < 4; r++) o[nt][r] = 0.f;
    float m0 = -1e30f, m1 = -1e30f, l0 = 0.f, l1 = 0.f;

    const int gi0 = q0 + w * 16 + gr;
    const int gi1 = gi0 + 8;
    const int NT  = (q0 + 128) / 64;

    const int qa_r = w * 16 + (lane & 15);
    const int qa_c = (lane >> 4) * 8;
    const int kb_r = lane & 7;
    const int kb_c = ((lane >> 3) & 1) * 8;
    const int v_r  = lane & 15;
    const int v_c8 = ((lane >> 4) & 1) * 8;

    for (int t = 0; t < NT; t++) {
        const int k0  = t * 64;
        const int buf = t & 1;
        if (t + 1 < NT) {
            const int nb = buf ^ 1;
            const size_t gb = ((size_t)(b * SEQ + (t + 1) * 64) * NH + h) * DHEAD;
            int idx = tid;
#pragma unroll
            for (int u = 0; u < 2; u++, idx += 256) {
                int row = idx >> 3, seg = (idx & 7) * 8;
                size_t go = gb + (size_t)row * HD + seg;
                uint32_t so = sb + (uint32_t)((KV_OFF + nb*KV_BUF + row*AT_SA + seg) * 2);
                CP16(so + 0*KV_ARR*2, Kh + go);
                CP16(so + 1*KV_ARR*2, Kl + go);
                CP16(so + 2*KV_ARR*2, Vh + go);
                CP16(so + 3*KV_ARR*2, Vl + go);
            }
            CPCOMMIT();
            CPWAIT1();
        } else {
            CPWAIT0();
        }
        __syncthreads();

        if (k0 <= q0 + w * 16 + 15) {
            const uint32_t kvb = sb + (uint32_t)((KV_OFF + buf * KV_BUF) * 2);

            float s[8][4];
#pragma unroll
            for (int nt = 0; nt < 8; nt++)
#pragma unroll
                for (int r = 0; r < 4; r++) s[nt][r] = 0.f;

#pragma unroll
            for (int ks = 0; ks < 4; ks++) {
                const int kc = ks * 16;
                uint32_t qh4[4], ql4[4];
                LDMX4(qh4, sb + (uint32_t)((qa_r * AT_SA + kc + qa_c) * 2));
                LDMX4(ql4, sb + (uint32_t)((Q_ELEMS + qa_r * AT_SA + kc + qa_c) * 2));
#pragma unroll
                for (int nt = 0; nt < 8; nt++) {
                    uint32_t kh2[2], kl2[2];
                    uint32_t bd = kvb + (uint32_t)(((nt*8 + kb_r) * AT_SA + kc + kb_c) * 2);
                    LDMX2(kh2, bd);
                    LDMX2(kl2, bd + KV_ARR * 2);
                    mma16816(s[nt], qh4, kh2[0], kh2[1]);
                    mma16816(s[nt], qh4, kl2[0], kl2[1]);
                    mma16816(s[nt], ql4, kh2[0], kh2[1]);
                }
            }

            const bool need_mask = (k0 + 63 > q0 + w * 16);
#pragma unroll
            for (int nt = 0; nt < 8; nt++) {
                const int c0 = k0 + nt * 8 + tid4 * 2;
                const int c1 = c0 + 1;
                float v0 = s[nt][0] * F_LOG2E, v1 = s[nt][1] * F_LOG2E;
                float v2 = s[nt][2] * F_LOG2E, v3 = s[nt][3] * F_LOG2E;
                if (need_mask) {
                    if (c0 > gi0) v0 = -1e30f;
                    if (c1 > gi0) v1 = -1e30f;
                    if (c0 > gi1) v2 = -1e30f;
                    if (c1 > gi1) v3 = -1e30f;
                }
                s[nt][0] = v0; s[nt][1] = v1; s[nt][2] = v2; s[nt][3] = v3;
            }

            float mx0 = -1e30f, mx1 = -1e30f;
#pragma unroll
            for (int nt = 0; nt < 8; nt++) {
                mx0 = fmaxf(mx0, fmaxf(s[nt][0], s[nt][1]));
                mx1 = fmaxf(mx1, fmaxf(s[nt][2], s[nt][3]));
            }
            mx0 = fmaxf(mx0, __shfl_xor_sync(0xffffffffu, mx0, 1));
            mx0 = fmaxf(mx0, __shfl_xor_sync(0xffffffffu, mx0, 2));
            mx1 = fmaxf(mx1, __shfl_xor_sync(0xffffffffu, mx1, 1));
            mx1 = fmaxf(mx1, __shfl_xor_sync(0xffffffffu, mx1, 2));
            const float mn0 = fmaxf(m0, mx0), mn1 = fmaxf(m1, mx1);
            const float a0 = exp2f(m0 - mn0), a1 = exp2f(m1 - mn1);
            m0 = mn0; m1 = mn1;

            float rs0 = 0.f, rs1 = 0.f;
#pragma unroll
            for (int nt = 0; nt < 8; nt++) {
                s[nt][0] = exp2f(s[nt][0] - mn0);
                s[nt][1] = exp2f(s[nt][1] - mn0);
                s[nt][2] = exp2f(s[nt][2] - mn1);
                s[nt][3] = exp2f(s[nt][3] - mn1);
                rs0 += s[nt][0] + s[nt][1];
                rs1 += s[nt][2] + s[nt][3];
            }
            rs0 += __shfl_xor_sync(0xffffffffu, rs0, 1);
            rs0 += __shfl_xor_sync(0xffffffffu, rs0, 2);
            rs1 += __shfl_xor_sync(0xffffffffu, rs1, 1);
            rs1 += __shfl_xor_sync(0xffffffffu, rs1, 2);
            l0 = l0 * a0 + rs0;
            l1 = l1 * a1 + rs1;
#pragma unroll
            for (int nt = 0; nt < 8; nt++) {
                o[nt][0] *= a0; o[nt][1] *= a0;
                o[nt][2] *= a1; o[nt][3] *= a1;
            }

            const uint32_t vhb = kvb + 2*KV_ARR*2;
            const uint32_t vlb = kvb + 3*KV_ARR*2;
#pragma unroll
            for (int ks = 0; ks < 4; ks++) {
                uint32_t pa[4], pb[4];
#pragma unroll
                for (int half = 0; half < 2; half++) {
                    const float* sp = s[2*ks + half];
#pragma unroll
                    for (int rp = 0; rp < 2; rp++) {
                        float f0 = sp[rp*2+0], f1 = sp[rp*2+1];
                        __nv_bfloat16 h0 = __float2bfloat16(f0);
                        __nv_bfloat16 h1 = __float2bfloat16(f1);
                        __nv_bfloat162 hp(h0, h1);
                        __nv_bfloat162 lp(__float2bfloat16(f0 - __bfloat162float(h0)),
                                          __float2bfloat16(f1 - __bfloat162float(h1)));
                        pa[half*2 + rp] = *(uint32_t*)&hp;
                        pb[half*2 + rp] = *(uint32_t*)&lp;
                    }
                }
                const int krow = ks * 16 + v_r;
#pragma unroll
                for (int db = 0; db < 4; db++) {
                    uint32_t vh4[4], vl4[4];
                    uint32_t va = (uint32_t)((krow * AT_SA + db * 16 + v_c8) * 2);
                    LDMX4T(vh4, vhb + va);
                    LDMX4T(vl4, vlb + va);
                    mma16816(o[db*2],   pa, vh4[0], vh4[1]);
                    mma16816(o[db*2],   pa, vl4[0], vl4[1]);
                    mma16816(o[db*2],   pb, vh4[0], vh4[1]);
                    mma16816(o[db*2+1], pa, vh4[2], vh4[3]);
                    mma16816(o[db*2+1], pa, vl4[2], vl4[3]);
                    mma16816(o[db*2+1], pb, vh4[2], vh4[3]);
                }
            }
        }
        __syncthreads();
    }

    const float i0 = 1.f / l0, i1 = 1.f / l1;
    const size_t t0 = (size_t)(b * SEQ + gi0) * HD + h * DHEAD + tid4 * 2;
    const size_t t1 = (size_t)(b * SEQ + gi1) * HD + h * DHEAD + tid4 * 2;
#pragma unroll
    for (int nt = 0; nt < 8; nt++) {
        float f0 = o[nt][0] * i0, f1 = o[nt][1] * i0;
        float f2 = o[nt][2] * i1, f3 = o[nt][3] * i1;
        __nv_bfloat16 h0 = __float2bfloat16(f0), h1 = __float2bfloat16(f1);
        __nv_bfloat16 h2 = __float2bfloat16(f2), h3 = __float2bfloat16(f3);
        __nv_bfloat162 hp0(h0, h1), hp1(h2, h3);
        __nv_bfloat162 lp0(__float2bfloat16(f0 - __bfloat162float(h0)),
                           __float2bfloat16(f1 - __bfloat162float(h1)));
        __nv_bfloat162 lp1(__float2bfloat16(f2 - __bfloat162float(h2)),
                           __float2bfloat16(f3 - __bfloat162float(h3)));
        *(uint32_t*)(Oh + t0 + nt*8) = *(uint32_t*)&hp0;
        *(uint32_t*)(Ol + t0 + nt*8) = *(uint32_t*)&lp0;
        *(uint32_t*)(Oh + t1 + nt*8) = *(uint32_t*)&hp1;
        *(uint32_t*)(Ol + t1 + nt*8) = *(uint32_t*)&lp1;
    }
}

// ---------------------------------------------------------------------------
extern "C" void kernel_launch(void* const* d_in, const int* in_sizes, int n_in,
                              void* d_out, int out_size)
{
    const float* x_q = (const float*)d_in[0];
    const float* x_k = (const float*)d_in[1];
    const float* x_v = (const float*)d_in[2];
    const float* Wq  = (const float*)d_in[4];
    const float* Wk  = (const float*)d_in[5];
    const float* Wv  = (const float*)d_in[6];
    const float* Wo  = (const float*)d_in[7];
    float* out = (float*)d_out;

    cudaFuncSetAttribute(tgemm_qkv, cudaFuncAttributeMaxDynamicSharedMemorySize,
                         GEMM_SMEM_B);
    cudaFuncSetAttribute(tgemm_out, cudaFuncAttributeMaxDynamicSharedMemorySize,
                         GEMM_SMEM_B);
    cudaFuncSetAttribute(attn_mma, cudaFuncAttributeMaxDynamicSharedMemorySize,
                         AT_SMEM_B);

    const int n4 = MTOT * DIM / 4;

    // weight transpose+split (all four) and input splits (all three)
    split_wT4<<<dim3(DIM / 32, DIM / 32, 4), dim3(32, 8)>>>(Wq, Wk, Wv, Wo);
    split_act3<<<dim3(n4 / 256, 3), 256>>>(
        (const float4*)x_q, (const float4*)x_k, (const float4*)x_v, n4);

    // fused QKV projections (grid.z = 3)
    tgemm_qkv<<<dim3(DIM / 128, MTOT / 128, 3), 256, GEMM_SMEM_B>>>();

    // attention
    attn_mma<<<dim3(SEQ / 128, BATCH * NH), 256, AT_SMEM_B>>>();

    // output projection
    tgemm_out<<<dim3(DIM / 128, MTOT / 128), 256, GEMM_SMEM_B>>>(out);
}

// round 12
// speedup vs baseline: 2.7973x; 1.0027x over previous
#include <cuda_runtime.h>
#include <cuda_bf16.h>
#include <cstdint>
#include <math.h>

#define BATCH 4
#define SEQ   2048
#define DIM   1024
#define NH    16
#define DHEAD 64
#define HD    (NH*DHEAD)       // 1024
#define MTOT  (BATCH*SEQ)      // 8192

// ---------------------------------------------------------------------------
// Device-global scratch (allocation-free per harness rules)
// ---------------------------------------------------------------------------
__device__ __nv_bfloat16 g_xh[3][(size_t)MTOT*DIM];  // split inputs hi (q,k,v)
__device__ __nv_bfloat16 g_xl[3][(size_t)MTOT*DIM];  // split inputs lo
__device__ __nv_bfloat16 g_oh[3][(size_t)MTOT*HD];   // projected q,k,v hi
__device__ __nv_bfloat16 g_ol[3][(size_t)MTOT*HD];   // projected q,k,v lo
__device__ __nv_bfloat16 g_ah[(size_t)MTOT*DIM];     // attention out hi
__device__ __nv_bfloat16 g_al[(size_t)MTOT*DIM];     // attention out lo
__device__ __nv_bfloat16 g_wth[4][(size_t)DIM*DIM];  // W^T hi [N][K]
__device__ __nv_bfloat16 g_wtl[4][(size_t)DIM*DIM];  // W^T lo [N][K]

// ---------------------------------------------------------------------------
// PTX helpers (baseline compute_103-safe)
// ---------------------------------------------------------------------------
__device__ __forceinline__ uint32_t smem_u32(const void* p) {
    uint32_t a;
    asm("{ .reg .u64 t; cvta.to.shared.u64 t, %1; cvt.u32.u64 %0, t; }"
        : "=r"(a) : "l"(p));
    return a;
}

#define LDMX4(r, addr) \
    asm volatile("ldmatrix.sync.aligned.m8n8.x4.shared.b16 {%0,%1,%2,%3}, [%4];" \
        : "=r"((r)[0]), "=r"((r)[1]), "=r"((r)[2]), "=r"((r)[3]) : "r"(addr))
#define LDMX4T(r, addr) \
    asm volatile("ldmatrix.sync.aligned.m8n8.x4.trans.shared.b16 {%0,%1,%2,%3}, [%4];" \
        : "=r"((r)[0]), "=r"((r)[1]), "=r"((r)[2]), "=r"((r)[3]) : "r"(addr))
#define LDMX2(r, addr) \
    asm volatile("ldmatrix.sync.aligned.m8n8.x2.shared.b16 {%0,%1}, [%2];" \
        : "=r"((r)[0]), "=r"((r)[1]) : "r"(addr))

#define CP16(dst, src) \
    asm volatile("cp.async.cg.shared.global [%0], [%1], 16;" \
        :: "r"(dst), "l"(src))
#define CPCOMMIT() asm volatile("cp.async.commit_group;" ::: "memory")
#define CPWAIT0()  asm volatile("cp.async.wait_group 0;" ::: "memory")
#define CPWAIT1()  asm volatile("cp.async.wait_group 1;" ::: "memory")

__device__ __forceinline__ void mma16816(float* d, const uint32_t* a,
                                         uint32_t b0, uint32_t b1) {
    asm volatile(
        "mma.sync.aligned.m16n8k16.row.col.f32.bf16.bf16.f32 "
        "{%0,%1,%2,%3}, {%4,%5,%6,%7}, {%8,%9}, {%0,%1,%2,%3};"
        : "+f"(d[0]), "+f"(d[1]), "+f"(d[2]), "+f"(d[3])
        : "r"(a[0]), "r"(a[1]), "r"(a[2]), "r"(a[3]), "r"(b0), "r"(b1));
}

// ---------------------------------------------------------------------------
// fp32 -> bf16 hi/lo split: fused over 3 inputs via blockIdx.y
// ---------------------------------------------------------------------------
__global__ __launch_bounds__(256) void split_act3(
    const float4* __restrict__ xq, const float4* __restrict__ xk,
    const float4* __restrict__ xv, int n4)
{
    int i = blockIdx.x * blockDim.x + threadIdx.x;
    if (i >= n4) return;
    const int z = blockIdx.y;
    const float4* x = (z == 0) ? xq : (z == 1) ? xk : xv;
    __nv_bfloat162* hi = (__nv_bfloat162*)g_xh[z];
    __nv_bfloat162* lo = (__nv_bfloat162*)g_xl[z];
    float4 v = x[i];
    __nv_bfloat16 hx = __float2bfloat16(v.x);
    __nv_bfloat16 hy = __float2bfloat16(v.y);
    __nv_bfloat16 hz = __float2bfloat16(v.z);
    __nv_bfloat16 hw = __float2bfloat16(v.w);
    hi[2*i]   = __nv_bfloat162(hx, hy);
    hi[2*i+1] = __nv_bfloat162(hz, hw);
    lo[2*i]   = __nv_bfloat162(__float2bfloat16(v.x - __bfloat162float(hx)),
                               __float2bfloat16(v.y - __bfloat162float(hy)));
    lo[2*i+1] = __nv_bfloat162(__float2bfloat16(v.z - __bfloat162float(hz)),
                               __float2bfloat16(v.w - __bfloat162float(hw)));
}

// Transpose + split 4 weights in one launch (blockIdx.z selects matrix)
__global__ __launch_bounds__(256) void split_wT4(
    const float* __restrict__ W0, const float* __restrict__ W1,
    const float* __restrict__ W2, const float* __restrict__ W3)
{
    __shared__ float t[32][33];
    const int z = blockIdx.z;
    const float* W = (z == 0) ? W0 : (z == 1) ? W1 : (z == 2) ? W2 : W3;
    __nv_bfloat16* Th = g_wth[z];
    __nv_bfloat16* Tl = g_wtl[z];
    int n0 = blockIdx.x * 32, k0 = blockIdx.y * 32;
    int tx = threadIdx.x, ty = threadIdx.y;   // block (32, 8)
#pragma unroll
    for (int j = 0; j < 32; j += 8)
        t[ty + j][tx] = W[(size_t)(k0 + ty + j) * DIM + n0 + tx];
    __syncthreads();
#pragma unroll
    for (int j = 0; j < 32; j += 8) {
        float v = t[tx][ty + j];
        __nv_bfloat16 h = __float2bfloat16(v);
        size_t o = (size_t)(n0 + ty + j) * DIM + k0 + tx;
        Th[o] = h;
        Tl[o] = __float2bfloat16(v - __bfloat162float(h));
    }
}

// ---------------------------------------------------------------------------
// bf16-split GEMM, cp.async 2-stage pipelined mainloop.
// CTA 128x128, 8 warps (2x4), warp 64x32, K chunk 32, 2 CTAs/SM.
// ---------------------------------------------------------------------------
#define KC    32
#define SA    40                  // 80B row stride: ldmatrix conflict-free
#define ARR   (128 * SA)          // 5120 elems per array
#define STAGE (4 * ARR)           // elems per stage
#define NCH   (DIM / KC)          // 32
#define GEMM_SMEM_B (2 * STAGE * 2)   // 81920 B

__device__ __forceinline__ void gemm_load_chunk(
    uint32_t sb, int st,
    const __nv_bfloat16* __restrict__ Ah, const __nv_bfloat16* __restrict__ Al,
    const __nv_bfloat16* __restrict__ Bh, const __nv_bfloat16* __restrict__ Bl,
    int bm, int bn, int k0)
{
    const int tid = threadIdx.x;
#pragma unroll
    for (int u = 0; u < 2; u++) {
        const int idx = tid + u * 256;
        const int row = idx >> 2;            // 0..127
        const int col = (idx & 3) * 8;       // 0,8,16,24
        const uint32_t so = sb + (uint32_t)((st * STAGE + row * SA + col) * 2);
        const size_t ga = (size_t)(bm + row) * DIM + k0 + col;
        const size_t gb = (size_t)(bn + row) * DIM + k0 + col;
        CP16(so + 0*ARR*2, Ah + ga);
        CP16(so + 1*ARR*2, Al + ga);
        CP16(so + 2*ARR*2, Bh + gb);
        CP16(so + 3*ARR*2, Bl + gb);
    }
}

__device__ __forceinline__ void gemm_mainloop(
    uint32_t sb,
    const __nv_bfloat16* __restrict__ Ah, const __nv_bfloat16* __restrict__ Al,
    const __nv_bfloat16* __restrict__ Bh, const __nv_bfloat16* __restrict__ Bl,
    int bm, int bn, float acc[4][4][4])
{
    const int lane = threadIdx.x & 31;
    const int warp = threadIdx.x >> 5;
    const int wm   = (warp & 1) * 64;
    const int wn   = (warp >> 1) * 32;
    const int a_r = wm + (lane & 15);
    const int a_c = (lane >> 4) * 8;
    const int b_r = wn + (lane & 7);
    const int b_c = ((lane >> 3) & 1) * 8;

    gemm_load_chunk(sb, 0, Ah, Al, Bh, Bl, bm, bn, 0);
    CPCOMMIT();

    for (int c = 0; c < NCH; c++) {
        const int st = c & 1;
        if (c + 1 < NCH) {
            gemm_load_chunk(sb, st ^ 1, Ah, Al, Bh, Bl, bm, bn, (c + 1) * KC);
            CPCOMMIT();
            CPWAIT1();
        } else {
            CPWAIT0();
        }
        __syncthreads();

        const int stOff = st * STAGE;
#pragma unroll
        for (int ks = 0; ks < KC / 16; ks++) {
            const int kc = ks * 16;
            uint32_t af[4][4], bh2[4][2], bl2[4][2];
#pragma unroll
            for (int mt = 0; mt < 4; mt++) {
                uint32_t ad = sb + (uint32_t)((stOff + (a_r + mt*16) * SA + kc + a_c) * 2);
                LDMX4(af[mt], ad);
            }
#pragma unroll
            for (int nt = 0; nt < 4; nt++) {
                uint32_t bd = sb + (uint32_t)((stOff + 2*ARR + (b_r + nt*8) * SA + kc + b_c) * 2);
                LDMX2(bh2[nt], bd);
                LDMX2(bl2[nt], bd + ARR * 2);
            }
#pragma unroll
            for (int mt = 0; mt < 4; mt++)
#pragma unroll
                for (int nt = 0; nt < 4; nt++) {
                    mma16816(acc[mt][nt], af[mt], bh2[nt][0], bh2[nt][1]);
                    mma16816(acc[mt][nt], af[mt], bl2[nt][0], bl2[nt][1]);
                }
#pragma unroll
            for (int mt = 0; mt < 4; mt++) {
                uint32_t ad = sb + (uint32_t)((stOff + ARR + (a_r + mt*16) * SA + kc + a_c) * 2);
                LDMX4(af[mt], ad);
            }
#pragma unroll
            for (int mt = 0; mt < 4; mt++)
#pragma unroll
                for (int nt = 0; nt < 4; nt++)
                    mma16816(acc[mt][nt], af[mt], bh2[nt][0], bh2[nt][1]);
        }
        __syncthreads();
    }
}

// Fused QKV projection: blockIdx.z selects input/weight/output set.
__global__ __launch_bounds__(256, 2) void tgemm_qkv()
{
    extern __shared__ __align__(16) __nv_bfloat16 sm[];
    const uint32_t sb = smem_u32(sm);
    const int z    = blockIdx.z;
    const int lane = threadIdx.x & 31;
    const int warp = threadIdx.x >> 5;
    const int wm = (warp & 1) * 64, wn = (warp >> 1) * 32;
    const int bm = blockIdx.y * 128, bn = blockIdx.x * 128;

    float acc[4][4][4];
#pragma unroll
    for (int mt = 0; mt < 4; mt++)
#pragma unroll
        for (int nt = 0; nt < 4; nt++)
#pragma unroll
            for (int r = 0; r < 4; r++) acc[mt][nt][r] = 0.f;

    gemm_mainloop(sb, g_xh[z], g_xl[z], g_wth[z], g_wtl[z], bm, bn, acc);

    __nv_bfloat16* Oh = g_oh[z];
    __nv_bfloat16* Ol = g_ol[z];
    const int gr = lane >> 2, tg = lane & 3;
#pragma unroll
    for (int mt = 0; mt < 4; mt++)
#pragma unroll
        for (int nt = 0; nt < 4; nt++)
#pragma unroll
            for (int hrow = 0; hrow < 2; hrow++) {
                float f0 = acc[mt][nt][hrow*2+0], f1 = acc[mt][nt][hrow*2+1];
                __nv_bfloat16 h0 = __float2bfloat16(f0);
                __nv_bfloat16 h1 = __float2bfloat16(f1);
                size_t o = (size_t)(bm + wm + mt*16 + gr + hrow*8) * DIM
                           + bn + wn + nt*8 + tg*2;
                __nv_bfloat162 hp(h0, h1);
                __nv_bfloat162 lp(__float2bfloat16(f0 - __bfloat162float(h0)),
                                  __float2bfloat16(f1 - __bfloat162float(h1)));
                *(uint32_t*)(Oh + o) = *(uint32_t*)&hp;
                *(uint32_t*)(Ol + o) = *(uint32_t*)&lp;
            }
}

// Output projection: A = attention out (g_ah/g_al), B = W^T[3], C fp32.
__global__ __launch_bounds__(256, 2) void tgemm_out(float* __restrict__ C)
{
    extern __shared__ __align__(16) __nv_bfloat16 sm[];
    const uint32_t sb = smem_u32(sm);
    const int lane = threadIdx.x & 31;
    const int warp = threadIdx.x >> 5;
    const int wm = (warp & 1) * 64, wn = (warp >> 1) * 32;
    const int bm = blockIdx.y * 128, bn = blockIdx.x * 128;

    float acc[4][4][4];
#pragma unroll
    for (int mt = 0; mt < 4; mt++)
#pragma unroll
        for (int nt = 0; nt < 4; nt++)
#pragma unroll
            for (int r = 0; r < 4; r++) acc[mt][nt][r] = 0.f;

    gemm_mainloop(sb, g_ah, g_al, g_wth[3], g_wtl[3], bm, bn, acc);

    const int gr = lane >> 2, tg = lane & 3;
#pragma unroll
    for (int mt = 0; mt < 4; mt++)
#pragma unroll
        for (int nt = 0; nt < 4; nt++) {
            float* p = C + (size_t)(bm + wm + mt*16 + gr) * DIM
                         + bn + wn + nt*8 + tg*2;
            *(float2*)p = make_float2(acc[mt][nt][0], acc[mt][nt][1]);
            *(float2*)(p + 8 * DIM) = make_float2(acc[mt][nt][2], acc[mt][nt][3]);
        }
}

// ---------------------------------------------------------------------------
// Flash attention on mma.sync, bf16 hi/lo split precision (as R7).
// ---------------------------------------------------------------------------
#define AT_SA   72
#define Q_ELEMS (128*AT_SA)
#define KV_ARR  (64*AT_SA)
#define KV_BUF  (4*KV_ARR)
#define KV_OFF  (2*Q_ELEMS)
#define AT_SMEM_B ((2*Q_ELEMS + 2*KV_BUF)*2)   // 110592 B
#define F_LOG2E 0.1803368801111204f            // SCALE * log2(e)

__global__ __launch_bounds__(256, 2) void attn_mma()
{
    extern __shared__ __align__(16) __nv_bfloat16 sa[];
    const __nv_bfloat16* __restrict__ Qh = g_oh[0];
    const __nv_bfloat16* __restrict__ Ql = g_ol[0];
    const __nv_bfloat16* __restrict__ Kh = g_oh[1];
    const __nv_bfloat16* __restrict__ Kl = g_ol[1];
    const __nv_bfloat16* __restrict__ Vh = g_oh[2];
    const __nv_bfloat16* __restrict__ Vl = g_ol[2];
    __nv_bfloat16* __restrict__ Oh = g_ah;
    __nv_bfloat16* __restrict__ Ol = g_al;

    const uint32_t sb = smem_u32(sa);
    const int tid  = threadIdx.x;
    const int lane = tid & 31;
    const int w    = tid >> 5;
    const int b    = blockIdx.y >> 4;
    const int h    = blockIdx.y & 15;
    const int qt   = (int)gridDim.x - 1 - (int)blockIdx.x;
    const int q0   = qt * 128;
    const int tid4 = lane & 3;
    const int gr   = lane >> 2;

    {   // prologue: KV tile 0 -> buf 0
        const size_t gb = ((size_t)(b * SEQ + 0) * NH + h) * DHEAD;
        int idx = tid;
#pragma unroll
        for (int u = 0; u < 2; u++, idx += 256) {
            int row = idx >> 3, seg = (idx & 7) * 8;
            size_t go = gb + (size_t)row * HD + seg;
            uint32_t so = sb + (uint32_t)((KV_OFF + row * AT_SA + seg) * 2);
            CP16(so + 0*KV_ARR*2, Kh + go);
            CP16(so + 1*KV_ARR*2, Kl + go);
            CP16(so + 2*KV_ARR*2, Vh + go);
            CP16(so + 3*KV_ARR*2, Vl + go);
        }
        CPCOMMIT();
    }
    {   // Q tile
        const size_t gq = ((size_t)(b * SEQ + q0) * NH + h) * DHEAD;
        int idx = tid;
#pragma unroll
        for (int u = 0; u < 4; u++, idx += 256) {
            int row = idx >> 3, seg = (idx & 7) * 8;
            size_t go = gq + (size_t)row * HD + seg;
            int so = row * AT_SA + seg;
            *(uint4*)&sa[so]           = *(const uint4*)(Qh + go);
            *(uint4*)&sa[Q_ELEMS + so] = *(const uint4*)(Ql + go);
        }
    }

    float o[8][4];
#pragma unroll
    for (int nt = 0; nt < 8; nt++)
#pragma unroll
        for (int r = 0; r < 4; r++) o[nt][r] = 0.f;
    float m0 = -1e30f, m1 = -1e30f, l0 = 0.f, l1 = 0.f;

    const int gi0 = q0 + w * 16 + gr;
    const int gi1 = gi0 + 8;
    const int NT  = (q0 + 128) / 64;

    const int qa_r = w * 16 + (lane & 15);
    const int qa_c = (lane >> 4) * 8;
    const int kb_r = lane & 7;
    const int kb_c = ((lane >> 3) & 1) * 8;
    const int v_r  = lane & 15;
    const int v_c8 = ((lane >> 4) & 1) * 8;

    for (int t = 0; t < NT; t++) {
        const int k0  = t * 64;
        const int buf = t & 1;
        if (t + 1 < NT) {
            const int nb = buf ^ 1;
            const size_t gb = ((size_t)(b * SEQ + (t + 1) * 64) * NH + h) * DHEAD;
            int idx = tid;
#pragma unroll
            for (int u = 0; u < 2; u++, idx += 256) {
                int row = idx >> 3, seg = (idx & 7) * 8;
                size_t go = gb + (size_t)row * HD + seg;
                uint32_t so = sb + (uint32_t)((KV_OFF + nb*KV_BUF + row*AT_SA + seg) * 2);
                CP16(so + 0*KV_ARR*2, Kh + go);
                CP16(so + 1*KV_ARR*2, Kl + go);
                CP16(so + 2*KV_ARR*2, Vh + go);
                CP16(so + 3*KV_ARR*2, Vl + go);
            }
            CPCOMMIT();
            CPWAIT1();
        } else {
            CPWAIT0();
        }
        __syncthreads();

        if (k0 <= q0 + w * 16 + 15) {
            const uint32_t kvb = sb + (uint32_t)((KV_OFF + buf * KV_BUF) * 2);

            float s[8][4];
#pragma unroll
            for (int nt = 0; nt < 8; nt++)
#pragma unroll
                for (int r = 0; r < 4; r++) s[nt][r] = 0.f;

#pragma unroll
            for (int ks = 0; ks < 4; ks++) {
                const int kc = ks * 16;
                uint32_t qh4[4], ql4[4];
                LDMX4(qh4, sb + (uint32_t)((qa_r * AT_SA + kc + qa_c) * 2));
                LDMX4(ql4, sb + (uint32_t)((Q_ELEMS + qa_r * AT_SA + kc + qa_c) * 2));
#pragma unroll
                for (int nt = 0; nt < 8; nt++) {
                    uint32_t kh2[2], kl2[2];
                    uint32_t bd = kvb + (uint32_t)(((nt*8 + kb_r) * AT_SA + kc + kb_c) * 2);
                    LDMX2(kh2, bd);
                    LDMX2(kl2, bd + KV_ARR * 2);
                    mma16816(s[nt], qh4, kh2[0], kh2[1]);
                    mma16816(s[nt], qh4, kl2[0], kl2[1]);
                    mma16816(s[nt], ql4, kh2[0], kh2[1]);
                }
            }

            const bool need_mask = (k0 + 63 > q0 + w * 16);
#pragma unroll
            for (int nt = 0; nt < 8; nt++) {
                const int c0 = k0 + nt * 8 + tid4 * 2;
                const int c1 = c0 + 1;
                float v0 = s[nt][0] * F_LOG2E, v1 = s[nt][1] * F_LOG2E;
                float v2 = s[nt][2] * F_LOG2E, v3 = s[nt][3] * F_LOG2E;
                if (need_mask) {
                    if (c0 > gi0) v0 = -1e30f;
                    if (c1 > gi0) v1 = -1e30f;
                    if (c0 > gi1) v2 = -1e30f;
                    if (c1 > gi1) v3 = -1e30f;
                }
                s[nt][0] = v0; s[nt][1] = v1; s[nt][2] = v2; s[nt][3] = v3;
            }

            float mx0 = -1e30f, mx1 = -1e30f;
#pragma unroll
            for (int nt = 0; nt < 8; nt++) {
                mx0 = fmaxf(mx0, fmaxf(s[nt][0], s[nt][1]));
                mx1 = fmaxf(mx1, fmaxf(s[nt][2], s[nt][3]));
            }
            mx0 = fmaxf(mx0, __shfl_xor_sync(0xffffffffu, mx0, 1));
            mx0 = fmaxf(mx0, __shfl_xor_sync(0xffffffffu, mx0, 2));
            mx1 = fmaxf(mx1, __shfl_xor_sync(0xffffffffu, mx1, 1));
            mx1 = fmaxf(mx1, __shfl_xor_sync(0xffffffffu, mx1, 2));
            const float mn0 = fmaxf(m0, mx0), mn1 = fmaxf(m1, mx1);
            const float a0 = exp2f(m0 - mn0), a1 = exp2f(m1 - mn1);
            m0 = mn0; m1 = mn1;

            float rs0 = 0.f, rs1 = 0.f;
#pragma unroll
            for (int nt = 0; nt < 8; nt++) {
                s[nt][0] = exp2f(s[nt][0] - mn0);
                s[nt][1] = exp2f(s[nt][1] - mn0);
                s[nt][2] = exp2f(s[nt][2] - mn1);
                s[nt][3] = exp2f(s[nt][3] - mn1);
                rs0 += s[nt][0] + s[nt][1];
                rs1 += s[nt][2] + s[nt][3];
            }
            rs0 += __shfl_xor_sync(0xffffffffu, rs0, 1);
            rs0 += __shfl_xor_sync(0xffffffffu, rs0, 2);
            rs1 += __shfl_xor_sync(0xffffffffu, rs1, 1);
            rs1 += __shfl_xor_sync(0xffffffffu, rs1, 2);
            l0 = l0 * a0 + rs0;
            l1 = l1 * a1 + rs1;
#pragma unroll
            for (int nt = 0; nt < 8; nt++) {
                o[nt][0] *= a0; o[nt][1] *= a0;
                o[nt][2] *= a1; o[nt][3] *= a1;
            }

            const uint32_t vhb = kvb + 2*KV_ARR*2;
            const uint32_t vlb = kvb + 3*KV_ARR*2;
#pragma unroll
            for (int ks = 0; ks < 4; ks++) {
                uint32_t pa[4], pb[4];
#pragma unroll
                for (int half = 0; half < 2; half++) {
                    const float* sp = s[2*ks + half];
#pragma unroll
                    for (int rp = 0; rp < 2; rp++) {
                        float f0 = sp[rp*2+0], f1 = sp[rp*2+1];
                        __nv_bfloat16 h0 = __float2bfloat16(f0);
                        __nv_bfloat16 h1 = __float2bfloat16(f1);
                        __nv_bfloat162 hp(h0, h1);
                        __nv_bfloat162 lp(__float2bfloat16(f0 - __bfloat162float(h0)),
                                          __float2bfloat16(f1 - __bfloat162float(h1)));
                        pa[half*2 + rp] = *(uint32_t*)&hp;
                        pb[half*2 + rp] = *(uint32_t*)&lp;
                    }
                }
                const int krow = ks * 16 + v_r;
#pragma unroll
                for (int db = 0; db < 4; db++) {
                    uint32_t vh4[4], vl4[4];
                    uint32_t va = (uint32_t)((krow * AT_SA + db * 16 + v_c8) * 2);
                    LDMX4T(vh4, vhb + va);
                    LDMX4T(vl4, vlb + va);
                    mma16816(o[db*2],   pa, vh4[0], vh4[1]);
                    mma16816(o[db*2],   pa, vl4[0], vl4[1]);
                    mma16816(o[db*2],   pb, vh4[0], vh4[1]);
                    mma16816(o[db*2+1], pa, vh4[2], vh4[3]);
                    mma16816(o[db*2+1], pa, vl4[2], vl4[3]);
                    mma16816(o[db*2+1], pb, vh4[2], vh4[3]);
                }
            }
        }
        __syncthreads();
    }

    const float i0 = 1.f / l0, i1 = 1.f / l1;
    const size_t t0 = (size_t)(b * SEQ + gi0) * HD + h * DHEAD + tid4 * 2;
    const size_t t1 = (size_t)(b * SEQ + gi1) * HD + h * DHEAD + tid4 * 2;
#pragma unroll
    for (int nt = 0; nt < 8; nt++) {
        float f0 = o[nt][0] * i0, f1 = o[nt][1] * i0;
        float f2 = o[nt][2] * i1, f3 = o[nt][3] * i1;
        __nv_bfloat16 h0 = __float2bfloat16(f0), h1 = __float2bfloat16(f1);
        __nv_bfloat16 h2 = __float2bfloat16(f2), h3 = __float2bfloat16(f3);
        __nv_bfloat162 hp0(h0, h1), hp1(h2, h3);
        __nv_bfloat162 lp0(__float2bfloat16(f0 - __bfloat162float(h0)),
                           __float2bfloat16(f1 - __bfloat162float(h1)));
        __nv_bfloat162 lp1(__float2bfloat16(f2 - __bfloat162float(h2)),
                           __float2bfloat16(f3 - __bfloat162float(h3)));
        *(uint32_t*)(Oh + t0 + nt*8) = *(uint32_t*)&hp0;
        *(uint32_t*)(Ol + t0 + nt*8) = *(uint32_t*)&lp0;
        *(uint32_t*)(Oh + t1 + nt*8) = *(uint32_t*)&hp1;
        *(uint32_t*)(Ol + t1 + nt*8) = *(uint32_t*)&lp1;
    }
}

// ---------------------------------------------------------------------------
extern "C" void kernel_launch(void* const* d_in, const int* in_sizes, int n_in,
                              void* d_out, int out_size)
{
    const float* x_q = (const float*)d_in[0];
    const float* x_k = (const float*)d_in[1];
    const float* x_v = (const float*)d_in[2];
    const float* Wq  = (const float*)d_in[4];
    const float* Wk  = (const float*)d_in[5];
    const float* Wv  = (const float*)d_in[6];
    const float* Wo  = (const float*)d_in[7];
    float* out = (float*)d_out;

    cudaFuncSetAttribute(tgemm_qkv, cudaFuncAttributeMaxDynamicSharedMemorySize,
                         GEMM_SMEM_B);
    cudaFuncSetAttribute(tgemm_out, cudaFuncAttributeMaxDynamicSharedMemorySize,
                         GEMM_SMEM_B);
    cudaFuncSetAttribute(attn_mma, cudaFuncAttributeMaxDynamicSharedMemorySize,
                         AT_SMEM_B);

    const int n4 = MTOT * DIM / 4;

    // weight transpose+split (all four) and input splits (all three)
    split_wT4<<<dim3(DIM / 32, DIM / 32, 4), dim3(32, 8)>>>(Wq, Wk, Wv, Wo);
    split_act3<<<dim3(n4 / 256, 3), 256>>>(
        (const float4*)x_q, (const float4*)x_k, (const float4*)x_v, n4);

    // fused QKV projections (grid.z = 3)
    tgemm_qkv<<<dim3(DIM / 128, MTOT / 128, 3), 256, GEMM_SMEM_B>>>();

    // attention
    attn_mma<<<dim3(SEQ / 128, BATCH * NH), 256, AT_SMEM_B>>>();

    // output projection
    tgemm_out<<<dim3(DIM / 128, MTOT / 128), 256, GEMM_SMEM_B>>>(out);
}